// round 5
// baseline (speedup 1.0000x reference)
#include <cuda_runtime.h>
#include <math.h>

#define Bdim 2
#define Tdim 2048
#define Edim 1024
#define Hdim 16
#define Ddim 64
#define Vdim 32000
#define BT   (Bdim * Tdim)   // 4096

// ---------------- scratch (static device globals; no allocation) -------------
__device__ float g_x[BT * Edim];
__device__ float g_q[BT * Edim];
__device__ float g_k[BT * Edim];
__device__ float g_v[BT * Edim];
__device__ float g_o[BT * Edim];
__device__ float g_rowloss[BT];

// ---------------- embed: x = tok_table[tok] + pos_emb[t] ---------------------
__global__ void embed_kernel(const int* __restrict__ tokens,
                             const float* __restrict__ tok_table,
                             const float* __restrict__ pos_emb) {
    int rowi = blockIdx.x;              // 0..4095  (b*T + t)
    int t = rowi & (Tdim - 1);
    int tok = tokens[rowi];
    const float4* tt = (const float4*)(tok_table + (size_t)tok * Edim);
    const float4* pp = (const float4*)(pos_emb + (size_t)t * Edim);
    float4* xx = (float4*)(g_x + (size_t)rowi * Edim);
    int i = threadIdx.x;                // 256 threads x float4 = 1024 floats
    float4 a = tt[i], b = pp[i];
    xx[i] = make_float4(a.x + b.x, a.y + b.y, a.z + b.z, a.w + b.w);
}

// ---------------- SGEMM  C[M,N] = A[M,K] * B[N,K]^T + bias[N] ---------------
// Both operands K-major => all global loads coalesced float4.
// BM=BN=128, BK=16, 256 threads, 8x8 per thread.
__global__ __launch_bounds__(256)
void sgemm_nt_kernel(const float* __restrict__ A, const float* __restrict__ B,
                     const float* __restrict__ bias, float* __restrict__ C,
                     int M, int N, int K) {
    __shared__ float As[16][128];
    __shared__ float Bs[16][128];
    const int tid = threadIdx.x;
    const int bm = blockIdx.y * 128, bn = blockIdx.x * 128;
    const int lr = tid >> 2;            // 0..63
    const int lc = (tid & 3) << 2;      // 0,4,8,12
    const int ty = tid >> 4, tx = tid & 15;

    float acc[8][8];
#pragma unroll
    for (int i = 0; i < 8; i++)
#pragma unroll
        for (int j = 0; j < 8; j++) acc[i][j] = 0.f;

    const float* Ab = A + (size_t)bm * K;
    const float* Bb = B + (size_t)bn * K;

    for (int k0 = 0; k0 < K; k0 += 16) {
        float4 a0 = *(const float4*)(Ab + (size_t)lr * K + k0 + lc);
        float4 a1 = *(const float4*)(Ab + (size_t)(lr + 64) * K + k0 + lc);
        float4 b0 = *(const float4*)(Bb + (size_t)lr * K + k0 + lc);
        float4 b1 = *(const float4*)(Bb + (size_t)(lr + 64) * K + k0 + lc);
        __syncthreads();
        As[lc + 0][lr] = a0.x; As[lc + 1][lr] = a0.y; As[lc + 2][lr] = a0.z; As[lc + 3][lr] = a0.w;
        As[lc + 0][lr + 64] = a1.x; As[lc + 1][lr + 64] = a1.y; As[lc + 2][lr + 64] = a1.z; As[lc + 3][lr + 64] = a1.w;
        Bs[lc + 0][lr] = b0.x; Bs[lc + 1][lr] = b0.y; Bs[lc + 2][lr] = b0.z; Bs[lc + 3][lr] = b0.w;
        Bs[lc + 0][lr + 64] = b1.x; Bs[lc + 1][lr + 64] = b1.y; Bs[lc + 2][lr + 64] = b1.z; Bs[lc + 3][lr + 64] = b1.w;
        __syncthreads();
#pragma unroll
        for (int k = 0; k < 16; k++) {
            float4 al = *(const float4*)&As[k][ty * 8];
            float4 ah = *(const float4*)&As[k][ty * 8 + 4];
            float4 bl = *(const float4*)&Bs[k][tx * 8];
            float4 bh = *(const float4*)&Bs[k][tx * 8 + 4];
            float ar[8] = {al.x, al.y, al.z, al.w, ah.x, ah.y, ah.z, ah.w};
            float br[8] = {bl.x, bl.y, bl.z, bl.w, bh.x, bh.y, bh.z, bh.w};
#pragma unroll
            for (int i = 0; i < 8; i++)
#pragma unroll
                for (int j = 0; j < 8; j++) acc[i][j] = fmaf(ar[i], br[j], acc[i][j]);
        }
    }

    float4 bvl = *(const float4*)(bias + bn + tx * 8);
    float4 bvh = *(const float4*)(bias + bn + tx * 8 + 4);
#pragma unroll
    for (int i = 0; i < 8; i++) {
        size_t off = (size_t)(bm + ty * 8 + i) * N + bn + tx * 8;
        float4 c0 = make_float4(acc[i][0] + bvl.x, acc[i][1] + bvl.y,
                                acc[i][2] + bvl.z, acc[i][3] + bvl.w);
        float4 c1 = make_float4(acc[i][4] + bvh.x, acc[i][5] + bvh.y,
                                acc[i][6] + bvh.z, acc[i][7] + bvh.w);
        *(float4*)(C + off) = c0;
        *(float4*)(C + off + 4) = c1;
    }
}

// ---------------- flash attention (causal + exact reference quirks) ----------
// BR=BS=64, 256 threads: thread = (row = tid>>2, q4 = tid&3).
// Each thread owns 16 s-columns (interleaved s = 4*jj + q4) and 16 d-columns
// (d = q4*16 .. +15) of its row.  Scale 1/sqrt(D) applied AFTER softmax.
#define ATTN_SMEM_FLOATS (3 * 64 * 68 + 64 * 65)
__global__ __launch_bounds__(256)
void attn_kernel(const float* __restrict__ Q, const float* __restrict__ Kg,
                 const float* __restrict__ Vg, float* __restrict__ O) {
    extern __shared__ float sm[];
    float* Qs = sm;                 // 64 x 68
    float* Ks = sm + 64 * 68;       // 64 x 68
    float* Vs = sm + 2 * 64 * 68;   // 64 x 68
    float* Ps = sm + 3 * 64 * 68;   // 64 x 65

    const int tid = threadIdx.x;
    const int row = tid >> 2, q4 = tid & 3;
    const int b = blockIdx.y >> 4, h = blockIdx.y & 15;
    const int t0 = blockIdx.x << 6;
    const int lc16 = q4 << 4;
    const size_t base = ((size_t)(b * Tdim + t0 + row)) * Edim + h * 64;

    {   // load Q tile
        const float4* src = (const float4*)(Q + base + lc16);
        float4* dst = (float4*)(Qs + row * 68 + lc16);
        dst[0] = src[0]; dst[1] = src[1]; dst[2] = src[2]; dst[3] = src[3];
    }
    __syncthreads();
    float4 qreg[16];
#pragma unroll
    for (int i = 0; i < 16; i++) qreg[i] = ((const float4*)(Qs + row * 68))[i];

    const int tg = t0 + row;
    float m_run = -INFINITY, l_run = 0.f;
    float4 o0 = {0, 0, 0, 0}, o1 = o0, o2 = o0, o3 = o0;

    const int ntiles = blockIdx.x + 1;
    for (int tile = 0; tile < ntiles; tile++) {
        const int s0 = tile << 6;
        __syncthreads();
        {   // load K,V tiles
            size_t kb = ((size_t)(b * Tdim + s0 + row)) * Edim + h * 64 + lc16;
            const float4* ks = (const float4*)(Kg + kb);
            const float4* vs = (const float4*)(Vg + kb);
            float4* kd = (float4*)(Ks + row * 68 + lc16);
            float4* vd = (float4*)(Vs + row * 68 + lc16);
            kd[0] = ks[0]; kd[1] = ks[1]; kd[2] = ks[2]; kd[3] = ks[3];
            vd[0] = vs[0]; vd[1] = vs[1]; vd[2] = vs[2]; vd[3] = vs[3];
        }
        __syncthreads();

        float sc[16];
#pragma unroll
        for (int jj = 0; jj < 16; jj++) {
            const int s = (jj << 2) | q4;
            const float4* kr = (const float4*)(Ks + s * 68);
            float acc = 0.f;
#pragma unroll
            for (int d = 0; d < 16; d++) {
                float4 kv = kr[d];
                acc = fmaf(qreg[d].x, kv.x, acc);
                acc = fmaf(qreg[d].y, kv.y, acc);
                acc = fmaf(qreg[d].z, kv.z, acc);
                acc = fmaf(qreg[d].w, kv.w, acc);
            }
            const int sg = s0 + s;
            // reference quirk: masked-out OR exactly-zero scores -> -inf
            sc[jj] = (sg <= tg && acc != 0.0f) ? acc : -INFINITY;
        }

        float mloc = sc[0];
#pragma unroll
        for (int jj = 1; jj < 16; jj++) mloc = fmaxf(mloc, sc[jj]);
        mloc = fmaxf(mloc, __shfl_xor_sync(0xffffffffu, mloc, 1));
        mloc = fmaxf(mloc, __shfl_xor_sync(0xffffffffu, mloc, 2));
        const float m_new = fmaxf(m_run, mloc);
        const float corr = __expf(m_run - m_new);
        float psum = 0.f;
#pragma unroll
        for (int jj = 0; jj < 16; jj++) {
            float p = __expf(sc[jj] - m_new);
            psum += p;
            Ps[row * 65 + ((jj << 2) | q4)] = p;
        }
        psum += __shfl_xor_sync(0xffffffffu, psum, 1);
        psum += __shfl_xor_sync(0xffffffffu, psum, 2);
        l_run = l_run * corr + psum;
        m_run = m_new;
        o0.x *= corr; o0.y *= corr; o0.z *= corr; o0.w *= corr;
        o1.x *= corr; o1.y *= corr; o1.z *= corr; o1.w *= corr;
        o2.x *= corr; o2.y *= corr; o2.z *= corr; o2.w *= corr;
        o3.x *= corr; o3.y *= corr; o3.z *= corr; o3.w *= corr;
        __syncwarp();   // Ps written by quad-mates

        const float* prow = Ps + row * 65;
#pragma unroll 8
        for (int s = 0; s < 64; s++) {
            const float pv = prow[s];
            const float4* vr = (const float4*)(Vs + s * 68 + lc16);
            float4 v0 = vr[0], v1 = vr[1], v2 = vr[2], v3 = vr[3];
            o0.x = fmaf(pv, v0.x, o0.x); o0.y = fmaf(pv, v0.y, o0.y);
            o0.z = fmaf(pv, v0.z, o0.z); o0.w = fmaf(pv, v0.w, o0.w);
            o1.x = fmaf(pv, v1.x, o1.x); o1.y = fmaf(pv, v1.y, o1.y);
            o1.z = fmaf(pv, v1.z, o1.z); o1.w = fmaf(pv, v1.w, o1.w);
            o2.x = fmaf(pv, v2.x, o2.x); o2.y = fmaf(pv, v2.y, o2.y);
            o2.z = fmaf(pv, v2.z, o2.z); o2.w = fmaf(pv, v2.w, o2.w);
            o3.x = fmaf(pv, v3.x, o3.x); o3.y = fmaf(pv, v3.y, o3.y);
            o3.z = fmaf(pv, v3.z, o3.z); o3.w = fmaf(pv, v3.w, o3.w);
        }
    }

    const float inv = 1.0f / (l_run * 8.0f);   // softmax normalize, THEN /sqrt(D)
    float4* op = (float4*)(O + base + lc16);
    op[0] = make_float4(o0.x * inv, o0.y * inv, o0.z * inv, o0.w * inv);
    op[1] = make_float4(o1.x * inv, o1.y * inv, o1.z * inv, o1.w * inv);
    op[2] = make_float4(o2.x * inv, o2.y * inv, o2.z * inv, o2.w * inv);
    op[3] = make_float4(o3.x * inv, o3.y * inv, o3.z * inv, o3.w * inv);
}

// ---------------- per-row NLL: rowloss = logsumexp(row) - logits[target] -----
__global__ __launch_bounds__(256)
void loss_row_kernel(const float* __restrict__ logits,
                     const int* __restrict__ targets,
                     float* __restrict__ rowloss) {
    __shared__ float red[256];
    const int row = blockIdx.x, tid = threadIdx.x;
    const float* lr = logits + (size_t)row * Vdim;
    const float4* lr4 = (const float4*)lr;

    float m = -INFINITY;
    for (int i = tid; i < Vdim / 4; i += 256) {
        float4 v = lr4[i];
        m = fmaxf(m, fmaxf(fmaxf(v.x, v.y), fmaxf(v.z, v.w)));
    }
    red[tid] = m; __syncthreads();
    for (int s = 128; s > 0; s >>= 1) {
        if (tid < s) red[tid] = fmaxf(red[tid], red[tid + s]);
        __syncthreads();
    }
    m = red[0]; __syncthreads();

    float sum = 0.f;
    for (int i = tid; i < Vdim / 4; i += 256) {
        float4 v = lr4[i];
        sum += __expf(v.x - m) + __expf(v.y - m) + __expf(v.z - m) + __expf(v.w - m);
    }
    red[tid] = sum; __syncthreads();
    for (int s = 128; s > 0; s >>= 1) {
        if (tid < s) red[tid] += red[tid + s];
        __syncthreads();
    }
    if (tid == 0)
        rowloss[row] = (m + __logf(red[0])) - lr[targets[row]];
}

__global__ __launch_bounds__(256)
void loss_reduce_kernel(const float* __restrict__ rowloss, float* __restrict__ out) {
    __shared__ float red[256];
    const int tid = threadIdx.x;
    float s = 0.f;
    for (int i = tid; i < BT; i += 256) s += rowloss[i];
    red[tid] = s; __syncthreads();
    for (int k = 128; k > 0; k >>= 1) {
        if (tid < k) red[tid] += red[tid + k];
        __syncthreads();
    }
    if (tid == 0) *out = red[0] / (float)BT;
}

// ---------------- launch ------------------------------------------------------
extern "C" void kernel_launch(void* const* d_in, const int* in_sizes, int n_in,
                              void* d_out, int out_size) {
    const int*   tokens    = (const int*)d_in[0];
    const int*   targets   = (const int*)d_in[1];
    const float* tok_table = (const float*)d_in[2];
    const float* pos_emb   = (const float*)d_in[3];
    const float* Wq        = (const float*)d_in[4];
    const float* bq        = (const float*)d_in[5];
    const float* Wk        = (const float*)d_in[6];
    const float* bk        = (const float*)d_in[7];
    const float* Wv        = (const float*)d_in[8];
    const float* bv        = (const float*)d_in[9];
    const float* Wo        = (const float*)d_in[10];
    const float* bo        = (const float*)d_in[11];
    float* out = (float*)d_out;

    float *px, *pq, *pk, *pv, *po, *prl;
    cudaGetSymbolAddress((void**)&px,  g_x);
    cudaGetSymbolAddress((void**)&pq,  g_q);
    cudaGetSymbolAddress((void**)&pk,  g_k);
    cudaGetSymbolAddress((void**)&pv,  g_v);
    cudaGetSymbolAddress((void**)&po,  g_o);
    cudaGetSymbolAddress((void**)&prl, g_rowloss);

    embed_kernel<<<BT, 256>>>(tokens, tok_table, pos_emb);

    dim3 gq(Edim / 128, BT / 128);
    sgemm_nt_kernel<<<gq, 256>>>(px, Wq, bq, pq, BT, Edim, Edim);
    sgemm_nt_kernel<<<gq, 256>>>(px, Wk, bk, pk, BT, Edim, Edim);
    sgemm_nt_kernel<<<gq, 256>>>(px, Wv, bv, pv, BT, Edim, Edim);

    cudaFuncSetAttribute(attn_kernel, cudaFuncAttributeMaxDynamicSharedMemorySize,
                         ATTN_SMEM_FLOATS * (int)sizeof(float));
    attn_kernel<<<dim3(Tdim / 64, Bdim * Hdim), 256,
                  ATTN_SMEM_FLOATS * sizeof(float)>>>(pq, pk, pv, po);

    dim3 gl(Vdim / 128, BT / 128);
    sgemm_nt_kernel<<<gl, 256>>>(po, Wo, bo, out, BT, Vdim, Edim);

    if ((long long)out_size > (long long)BT * Vdim) {
        loss_row_kernel<<<BT, 256>>>(out, targets, prl);
        loss_reduce_kernel<<<1, 256>>>(prl, out + (size_t)BT * Vdim);
    }
}

// round 9
// speedup vs baseline: 1.7621x; 1.7621x over previous
#include <cuda_runtime.h>
#include <cuda_bf16.h>
#include <math.h>
#include <stdint.h>

#define Bdim 2
#define Tdim 2048
#define Edim 1024
#define Hdim 16
#define Ddim 64
#define Vdim 32000
#define BT   (Bdim * Tdim)   // 4096

// ---------------- scratch (static device globals; no allocation) -------------
__device__ float g_q[BT * Edim];
__device__ float g_k[BT * Edim];
__device__ float g_v[BT * Edim];
__device__ float g_rowloss[BT];

// bf16 hi/lo split operands for tensor-core GEMMs
__device__ __nv_bfloat16 g_xh[BT * Edim], g_xl[BT * Edim];
__device__ __nv_bfloat16 g_oh[BT * Edim], g_ol[BT * Edim];
__device__ __nv_bfloat16 g_wqh[Edim * Edim], g_wql[Edim * Edim];
__device__ __nv_bfloat16 g_wkh[Edim * Edim], g_wkl[Edim * Edim];
__device__ __nv_bfloat16 g_wvh[Edim * Edim], g_wvl[Edim * Edim];
__device__ __nv_bfloat16 g_woh[Vdim * Edim], g_wol[Vdim * Edim];

// ---------------- small helpers ----------------------------------------------
__device__ __forceinline__ void split1(float v, __nv_bfloat16& h, __nv_bfloat16& l) {
    h = __float2bfloat16(v);
    l = __float2bfloat16(v - __bfloat162float(h));   // residual exact in fp32
}

__device__ __forceinline__ uint32_t smem_u32(const void* p) {
    uint32_t a;
    asm("{ .reg .u64 t; cvta.to.shared.u64 t, %1; cvt.u32.u64 %0, t; }" : "=r"(a) : "l"(p));
    return a;
}

__device__ __forceinline__ void ldsm4(uint32_t* r, uint32_t addr) {
    asm volatile("ldmatrix.sync.aligned.m8n8.x4.shared.b16 {%0,%1,%2,%3}, [%4];"
                 : "=r"(r[0]), "=r"(r[1]), "=r"(r[2]), "=r"(r[3]) : "r"(addr));
}

__device__ __forceinline__ void mma16816(float* c, const uint32_t* a, const uint32_t* b) {
    asm volatile("mma.sync.aligned.m16n8k16.row.col.f32.bf16.bf16.f32 "
                 "{%0,%1,%2,%3}, {%4,%5,%6,%7}, {%8,%9}, {%0,%1,%2,%3};"
                 : "+f"(c[0]), "+f"(c[1]), "+f"(c[2]), "+f"(c[3])
                 : "r"(a[0]), "r"(a[1]), "r"(a[2]), "r"(a[3]), "r"(b[0]), "r"(b[1]));
}

#define CP_ASYNC16(s, g) asm volatile("cp.async.cg.shared.global [%0], [%1], 16;" :: "r"(s), "l"(g))
#define CP_COMMIT()      asm volatile("cp.async.commit_group;")
#define CP_WAIT1()       asm volatile("cp.async.wait_group 1;")
#define CP_WAIT0()       asm volatile("cp.async.wait_group 0;")

// ---------------- embed: write hi/lo bf16 of tok_table[tok] + pos_emb[t] -----
__global__ void embed_kernel(const int* __restrict__ tokens,
                             const float* __restrict__ tok_table,
                             const float* __restrict__ pos_emb) {
    int rowi = blockIdx.x;
    int t = rowi & (Tdim - 1);
    int tok = tokens[rowi];
    const float4* tt = (const float4*)(tok_table + (size_t)tok * Edim);
    const float4* pp = (const float4*)(pos_emb + (size_t)t * Edim);
    int i = threadIdx.x;                // 256 threads x float4
    float4 a = tt[i], b = pp[i];
    float v[4] = {a.x + b.x, a.y + b.y, a.z + b.z, a.w + b.w};
    __nv_bfloat16 h[4], l[4];
#pragma unroll
    for (int j = 0; j < 4; j++) split1(v[j], h[j], l[j]);
    size_t off = (size_t)rowi * Edim + i * 4;
    *(uint2*)(g_xh + off) = *(uint2*)h;
    *(uint2*)(g_xl + off) = *(uint2*)l;
}

// ---------------- fp32 -> bf16 hi/lo split (weights) --------------------------
__global__ __launch_bounds__(256)
void split_kernel(const float* __restrict__ src, __nv_bfloat16* __restrict__ hi,
                  __nv_bfloat16* __restrict__ lo, int n4) {
    int i = blockIdx.x * 256 + threadIdx.x;
    int stride = gridDim.x * 256;
    const float4* s4 = (const float4*)src;
    for (; i < n4; i += stride) {
        float4 v = s4[i];
        float f[4] = {v.x, v.y, v.z, v.w};
        __nv_bfloat16 h[4], l[4];
#pragma unroll
        for (int j = 0; j < 4; j++) split1(f[j], h[j], l[j]);
        *(uint2*)(hi + (size_t)i * 4) = *(uint2*)h;
        *(uint2*)(lo + (size_t)i * 4) = *(uint2*)l;
    }
}

// ---------------- HMMA split-bf16 GEMM: C = A*B^T + bias ---------------------
// A[M,K], B[N,K] bf16 (hi,lo), K-major. CTA tile 128x128, BK=32, 8 warps,
// warp tile 64x32. 3-term split accumulated into fp32 mma accumulators.
#define KPB 80                      // smem bytes per row (32 bf16 + 8 pad)
#define MT_BYTES (128 * KPB)        // 10240 per matrix tile
#define TG_STAGE (4 * MT_BYTES)     // Ah, Al, Bh, Bl
#define TG_SMEM  (2 * TG_STAGE)     // double buffered: 81920 B

__global__ __launch_bounds__(256, 1)
void tgemm_kernel(const __nv_bfloat16* __restrict__ Ah, const __nv_bfloat16* __restrict__ Al,
                  const __nv_bfloat16* __restrict__ Bh, const __nv_bfloat16* __restrict__ Bl,
                  const float* __restrict__ bias, float* __restrict__ C,
                  int M, int N, int K, int swG) {
    extern __shared__ char smem[];
    const uint32_t sbase = smem_u32(smem);
    const int tid = threadIdx.x;
    const int lane = tid & 31, wid = tid >> 5;

    // tile coords with L2 swizzle (groups of swG m-tiles)
    const int nt_n = N >> 7;
    const int per = swG * nt_n;
    const int grp = blockIdx.x / per, rem = blockIdx.x % per;
    const int bm = (grp * swG + rem % swG) << 7;
    const int bn = (rem / swG) << 7;

    // ---- global->smem mapping: 512 16B chunks per matrix, 2 per thread ------
    const int c0 = tid, c1 = tid + 256;
    const int r0c = c0 >> 2, q0 = c0 & 3;      // row, 16B-seg
    const int r1c = c1 >> 2, q1 = c1 & 3;
    const uint32_t so00 = r0c * KPB + q0 * 16;
    const uint32_t so01 = r1c * KPB + q1 * 16;
    // global byte offsets (per matrix), advance by 64B per k-chunk
    const char* gAh = (const char*)Ah;  const char* gAl = (const char*)Al;
    const char* gBh = (const char*)Bh;  const char* gBl = (const char*)Bl;
    const size_t ga0 = ((size_t)(bm + r0c) * K + q0 * 8) * 2;
    const size_t ga1 = ((size_t)(bm + r1c) * K + q1 * 8) * 2;
    const size_t gb0 = ((size_t)(bn + r0c) * K + q0 * 8) * 2;
    const size_t gb1 = ((size_t)(bn + r1c) * K + q1 * 8) * 2;

    const int NK = K >> 5;   // BK = 32

#define LOAD_STAGE(buf, kc)                                                      \
    do {                                                                         \
        const uint32_t b_ = sbase + (buf) * TG_STAGE;                            \
        const size_t kb_ = (size_t)(kc) * 64;                                    \
        CP_ASYNC16(b_ + 0 * MT_BYTES + so00, gAh + ga0 + kb_);                   \
        CP_ASYNC16(b_ + 0 * MT_BYTES + so01, gAh + ga1 + kb_);                   \
        CP_ASYNC16(b_ + 1 * MT_BYTES + so00, gAl + ga0 + kb_);                   \
        CP_ASYNC16(b_ + 1 * MT_BYTES + so01, gAl + ga1 + kb_);                   \
        CP_ASYNC16(b_ + 2 * MT_BYTES + so00, gBh + gb0 + kb_);                   \
        CP_ASYNC16(b_ + 2 * MT_BYTES + so01, gBh + gb1 + kb_);                   \
        CP_ASYNC16(b_ + 3 * MT_BYTES + so00, gBl + gb0 + kb_);                   \
        CP_ASYNC16(b_ + 3 * MT_BYTES + so01, gBl + gb1 + kb_);                   \
    } while (0)

    // ---- warp compute mapping ----
    const int wm = (wid >> 2) * 64;        // 0 or 64
    const int wn = (wid & 3) * 32;         // 0,32,64,96
    const uint32_t arow = (lane & 7) | (((lane >> 3) & 1) << 3);
    const uint32_t akoff = (lane >> 4) * 16;
    const uint32_t brow = (lane & 7) + ((lane >> 4) << 3);
    const uint32_t bkoff = ((lane >> 3) & 1) * 16;

    float acc[4][4][4];
#pragma unroll
    for (int i = 0; i < 4; i++)
#pragma unroll
        for (int j = 0; j < 4; j++)
#pragma unroll
            for (int r = 0; r < 4; r++) acc[i][j][r] = 0.f;

    LOAD_STAGE(0, 0);
    CP_COMMIT();

    for (int kc = 0; kc < NK; kc++) {
        const int cur = kc & 1;
        if (kc + 1 < NK) {
            LOAD_STAGE(cur ^ 1, kc + 1);
            CP_COMMIT();
            CP_WAIT1();
        } else {
            CP_WAIT0();
        }
        __syncthreads();

        const uint32_t bufA = sbase + cur * TG_STAGE;
        const uint32_t bufB = bufA + 2 * MT_BYTES;
#pragma unroll
        for (int ks = 0; ks < 2; ks++) {
            const uint32_t koff = ks * 32;
            uint32_t ah[4][4], al[4][4];
#pragma unroll
            for (int i = 0; i < 4; i++) {
                uint32_t ad = bufA + (wm + i * 16 + arow) * KPB + koff + akoff;
                ldsm4(ah[i], ad);
                ldsm4(al[i], ad + MT_BYTES);
            }
            uint32_t bh[4][2], bl[4][2];
#pragma unroll
            for (int jj = 0; jj < 2; jj++) {
                uint32_t bd = bufB + (wn + jj * 16 + brow) * KPB + koff + bkoff;
                uint32_t t[4];
                ldsm4(t, bd);
                bh[2 * jj][0] = t[0]; bh[2 * jj][1] = t[1];
                bh[2 * jj + 1][0] = t[2]; bh[2 * jj + 1][1] = t[3];
                ldsm4(t, bd + MT_BYTES);
                bl[2 * jj][0] = t[0]; bl[2 * jj][1] = t[1];
                bl[2 * jj + 1][0] = t[2]; bl[2 * jj + 1][1] = t[3];
            }
#pragma unroll
            for (int i = 0; i < 4; i++)
#pragma unroll
                for (int j = 0; j < 4; j++) {
                    mma16816(acc[i][j], ah[i], bh[j]);
                    mma16816(acc[i][j], ah[i], bl[j]);
                    mma16816(acc[i][j], al[i], bh[j]);
                }
        }
        __syncthreads();
    }

    // ---- epilogue: add bias, write fp32 C ----
    const int er = bm + wm + (lane >> 2);
    const int ec = bn + wn + 2 * (lane & 3);
#pragma unroll
    for (int i = 0; i < 4; i++) {
#pragma unroll
        for (int j = 0; j < 4; j++) {
            const int row = er + i * 16, col = ec + j * 8;
            const float b0 = bias[col], b1 = bias[col + 1];
            float2 v0 = {acc[i][j][0] + b0, acc[i][j][1] + b1};
            float2 v1 = {acc[i][j][2] + b0, acc[i][j][3] + b1};
            *(float2*)(C + (size_t)row * N + col) = v0;
            *(float2*)(C + (size_t)(row + 8) * N + col) = v1;
        }
    }
#undef LOAD_STAGE
}

// ---------------- flash attention (causal + exact reference quirks) ----------
#define ATTN_SMEM_FLOATS (3 * 64 * 68 + 64 * 65)
__global__ __launch_bounds__(256)
void attn_kernel(const float* __restrict__ Q, const float* __restrict__ Kg,
                 const float* __restrict__ Vg) {
    extern __shared__ float sm[];
    float* Qs = sm;                 // 64 x 68
    float* Ks = sm + 64 * 68;
    float* Vs = sm + 2 * 64 * 68;
    float* Ps = sm + 3 * 64 * 68;   // 64 x 65

    const int tid = threadIdx.x;
    const int row = tid >> 2, q4 = tid & 3;
    const int b = blockIdx.y >> 4, h = blockIdx.y & 15;
    const int t0 = blockIdx.x << 6;
    const int lc16 = q4 << 4;
    const size_t base = ((size_t)(b * Tdim + t0 + row)) * Edim + h * 64;

    {
        const float4* src = (const float4*)(Q + base + lc16);
        float4* dst = (float4*)(Qs + row * 68 + lc16);
        dst[0] = src[0]; dst[1] = src[1]; dst[2] = src[2]; dst[3] = src[3];
    }
    __syncthreads();
    float4 qreg[16];
#pragma unroll
    for (int i = 0; i < 16; i++) qreg[i] = ((const float4*)(Qs + row * 68))[i];

    const int tg = t0 + row;
    float m_run = -INFINITY, l_run = 0.f;
    float4 o0 = {0, 0, 0, 0}, o1 = o0, o2 = o0, o3 = o0;

    const int ntiles = blockIdx.x + 1;
    for (int tile = 0; tile < ntiles; tile++) {
        const int s0 = tile << 6;
        __syncthreads();
        {
            size_t kb = ((size_t)(b * Tdim + s0 + row)) * Edim + h * 64 + lc16;
            const float4* ks = (const float4*)(Kg + kb);
            const float4* vs = (const float4*)(Vg + kb);
            float4* kd = (float4*)(Ks + row * 68 + lc16);
            float4* vd = (float4*)(Vs + row * 68 + lc16);
            kd[0] = ks[0]; kd[1] = ks[1]; kd[2] = ks[2]; kd[3] = ks[3];
            vd[0] = vs[0]; vd[1] = vs[1]; vd[2] = vs[2]; vd[3] = vs[3];
        }
        __syncthreads();

        float sc[16];
#pragma unroll
        for (int jj = 0; jj < 16; jj++) {
            const int s = (jj << 2) | q4;
            const float4* kr = (const float4*)(Ks + s * 68);
            float acc = 0.f;
#pragma unroll
            for (int d = 0; d < 16; d++) {
                float4 kv = kr[d];
                acc = fmaf(qreg[d].x, kv.x, acc);
                acc = fmaf(qreg[d].y, kv.y, acc);
                acc = fmaf(qreg[d].z, kv.z, acc);
                acc = fmaf(qreg[d].w, kv.w, acc);
            }
            const int sg = s0 + s;
            sc[jj] = (sg <= tg && acc != 0.0f) ? acc : -INFINITY;
        }

        float mloc = sc[0];
#pragma unroll
        for (int jj = 1; jj < 16; jj++) mloc = fmaxf(mloc, sc[jj]);
        mloc = fmaxf(mloc, __shfl_xor_sync(0xffffffffu, mloc, 1));
        mloc = fmaxf(mloc, __shfl_xor_sync(0xffffffffu, mloc, 2));
        const float m_new = fmaxf(m_run, mloc);
        const float corr = __expf(m_run - m_new);
        float psum = 0.f;
#pragma unroll
        for (int jj = 0; jj < 16; jj++) {
            float p = __expf(sc[jj] - m_new);
            psum += p;
            Ps[row * 65 + ((jj << 2) | q4)] = p;
        }
        psum += __shfl_xor_sync(0xffffffffu, psum, 1);
        psum += __shfl_xor_sync(0xffffffffu, psum, 2);
        l_run = l_run * corr + psum;
        m_run = m_new;
        o0.x *= corr; o0.y *= corr; o0.z *= corr; o0.w *= corr;
        o1.x *= corr; o1.y *= corr; o1.z *= corr; o1.w *= corr;
        o2.x *= corr; o2.y *= corr; o2.z *= corr; o2.w *= corr;
        o3.x *= corr; o3.y *= corr; o3.z *= corr; o3.w *= corr;
        __syncwarp();

        const float* prow = Ps + row * 65;
#pragma unroll 8
        for (int s = 0; s < 64; s++) {
            const float pv = prow[s];
            const float4* vr = (const float4*)(Vs + s * 68 + lc16);
            float4 v0 = vr[0], v1 = vr[1], v2 = vr[2], v3 = vr[3];
            o0.x = fmaf(pv, v0.x, o0.x); o0.y = fmaf(pv, v0.y, o0.y);
            o0.z = fmaf(pv, v0.z, o0.z); o0.w = fmaf(pv, v0.w, o0.w);
            o1.x = fmaf(pv, v1.x, o1.x); o1.y = fmaf(pv, v1.y, o1.y);
            o1.z = fmaf(pv, v1.z, o1.z); o1.w = fmaf(pv, v1.w, o1.w);
            o2.x = fmaf(pv, v2.x, o2.x); o2.y = fmaf(pv, v2.y, o2.y);
            o2.z = fmaf(pv, v2.z, o2.z); o2.w = fmaf(pv, v2.w, o2.w);
            o3.x = fmaf(pv, v3.x, o3.x); o3.y = fmaf(pv, v3.y, o3.y);
            o3.z = fmaf(pv, v3.z, o3.z); o3.w = fmaf(pv, v3.w, o3.w);
        }
    }

    const float inv = 1.0f / (l_run * 8.0f);   // normalize, THEN /sqrt(D)
    float vals[16] = {o0.x * inv, o0.y * inv, o0.z * inv, o0.w * inv,
                      o1.x * inv, o1.y * inv, o1.z * inv, o1.w * inv,
                      o2.x * inv, o2.y * inv, o2.z * inv, o2.w * inv,
                      o3.x * inv, o3.y * inv, o3.z * inv, o3.w * inv};
    __nv_bfloat16 hs[16], ls[16];
#pragma unroll
    for (int i = 0; i < 16; i++) split1(vals[i], hs[i], ls[i]);
    *(uint4*)(g_oh + base + lc16)     = ((uint4*)hs)[0];
    *(uint4*)(g_oh + base + lc16 + 8) = ((uint4*)hs)[1];
    *(uint4*)(g_ol + base + lc16)     = ((uint4*)ls)[0];
    *(uint4*)(g_ol + base + lc16 + 8) = ((uint4*)ls)[1];
}

// ---------------- per-row NLL -------------------------------------------------
__global__ __launch_bounds__(256)
void loss_row_kernel(const float* __restrict__ logits,
                     const int* __restrict__ targets,
                     float* __restrict__ rowloss) {
    __shared__ float red[256];
    const int row = blockIdx.x, tid = threadIdx.x;
    const float* lr = logits + (size_t)row * Vdim;
    const float4* lr4 = (const float4*)lr;

    float m = -INFINITY;
    for (int i = tid; i < Vdim / 4; i += 256) {
        float4 v = lr4[i];
        m = fmaxf(m, fmaxf(fmaxf(v.x, v.y), fmaxf(v.z, v.w)));
    }
    red[tid] = m; __syncthreads();
    for (int s = 128; s > 0; s >>= 1) {
        if (tid < s) red[tid] = fmaxf(red[tid], red[tid + s]);
        __syncthreads();
    }
    m = red[0]; __syncthreads();

    float sum = 0.f;
    for (int i = tid; i < Vdim / 4; i += 256) {
        float4 v = lr4[i];
        sum += __expf(v.x - m) + __expf(v.y - m) + __expf(v.z - m) + __expf(v.w - m);
    }
    red[tid] = sum; __syncthreads();
    for (int s = 128; s > 0; s >>= 1) {
        if (tid < s) red[tid] += red[tid + s];
        __syncthreads();
    }
    if (tid == 0)
        rowloss[row] = (m + __logf(red[0])) - lr[targets[row]];
}

__global__ __launch_bounds__(256)
void loss_reduce_kernel(const float* __restrict__ rowloss, float* __restrict__ out) {
    __shared__ float red[256];
    const int tid = threadIdx.x;
    float s = 0.f;
    for (int i = tid; i < BT; i += 256) s += rowloss[i];
    red[tid] = s; __syncthreads();
    for (int k = 128; k > 0; k >>= 1) {
        if (tid < k) red[tid] += red[tid + k];
        __syncthreads();
    }
    if (tid == 0) *out = red[0] / (float)BT;
}

// ---------------- launch ------------------------------------------------------
extern "C" void kernel_launch(void* const* d_in, const int* in_sizes, int n_in,
                              void* d_out, int out_size) {
    const int*   tokens    = (const int*)d_in[0];
    const int*   targets   = (const int*)d_in[1];
    const float* tok_table = (const float*)d_in[2];
    const float* pos_emb   = (const float*)d_in[3];
    const float* Wq        = (const float*)d_in[4];
    const float* bq        = (const float*)d_in[5];
    const float* Wk        = (const float*)d_in[6];
    const float* bk        = (const float*)d_in[7];
    const float* Wv        = (const float*)d_in[8];
    const float* bv        = (const float*)d_in[9];
    const float* Wo        = (const float*)d_in[10];
    const float* bo        = (const float*)d_in[11];
    float* out = (float*)d_out;

    float *pq, *pk, *pv, *prl;
    cudaGetSymbolAddress((void**)&pq,  g_q);
    cudaGetSymbolAddress((void**)&pk,  g_k);
    cudaGetSymbolAddress((void**)&pv,  g_v);
    cudaGetSymbolAddress((void**)&prl, g_rowloss);

    __nv_bfloat16 *pxh, *pxl, *poh, *pol;
    __nv_bfloat16 *pwqh, *pwql, *pwkh, *pwkl, *pwvh, *pwvl, *pwoh, *pwol;
    cudaGetSymbolAddress((void**)&pxh, g_xh);  cudaGetSymbolAddress((void**)&pxl, g_xl);
    cudaGetSymbolAddress((void**)&poh, g_oh);  cudaGetSymbolAddress((void**)&pol, g_ol);
    cudaGetSymbolAddress((void**)&pwqh, g_wqh); cudaGetSymbolAddress((void**)&pwql, g_wql);
    cudaGetSymbolAddress((void**)&pwkh, g_wkh); cudaGetSymbolAddress((void**)&pwkl, g_wkl);
    cudaGetSymbolAddress((void**)&pwvh, g_wvh); cudaGetSymbolAddress((void**)&pwvl, g_wvl);
    cudaGetSymbolAddress((void**)&pwoh, g_woh); cudaGetSymbolAddress((void**)&pwol, g_wol);

    cudaFuncSetAttribute(tgemm_kernel, cudaFuncAttributeMaxDynamicSharedMemorySize, TG_SMEM);
    cudaFuncSetAttribute(attn_kernel, cudaFuncAttributeMaxDynamicSharedMemorySize,
                         ATTN_SMEM_FLOATS * (int)sizeof(float));

    // embed (writes xh/xl directly) + weight splits
    embed_kernel<<<BT, 256>>>(tokens, tok_table, pos_emb);
    split_kernel<<<512, 256>>>(Wq, pwqh, pwql, Edim * Edim / 4);
    split_kernel<<<512, 256>>>(Wk, pwkh, pwkl, Edim * Edim / 4);
    split_kernel<<<512, 256>>>(Wv, pwvh, pwvl, Edim * Edim / 4);
    split_kernel<<<2048, 256>>>(Wo, pwoh, pwol, Vdim * Edim / 4);

    // QKV projections: [4096,1024] = x @ W^T + b
    const int gq = (BT / 128) * (Edim / 128);
    tgemm_kernel<<<gq, 256, TG_SMEM>>>(pxh, pxl, pwqh, pwql, bq, pq, BT, Edim, Edim, 8);
    tgemm_kernel<<<gq, 256, TG_SMEM>>>(pxh, pxl, pwkh, pwkl, bk, pk, BT, Edim, Edim, 8);
    tgemm_kernel<<<gq, 256, TG_SMEM>>>(pxh, pxl, pwvh, pwvl, bv, pv, BT, Edim, Edim, 8);

    // attention (writes oh/ol directly)
    attn_kernel<<<dim3(Tdim / 64, Bdim * Hdim), 256,
                  ATTN_SMEM_FLOATS * sizeof(float)>>>(pq, pk, pv);

    // logits: [4096,32000] = o @ Wo^T + bo
    const int gl = (BT / 128) * (Vdim / 128);
    tgemm_kernel<<<gl, 256, TG_SMEM>>>(poh, pol, pwoh, pwol, bo, out, BT, Vdim, Edim, 8);

    if ((long long)out_size > (long long)BT * Vdim) {
        loss_row_kernel<<<BT, 256>>>(out, targets, prl);
        loss_reduce_kernel<<<1, 256>>>(prl, out + (size_t)BT * Vdim);
    }
}

// round 13
// speedup vs baseline: 1.8112x; 1.0279x over previous
#include <cuda_runtime.h>
#include <cuda_bf16.h>
#include <math.h>
#include <stdint.h>

#define Bdim 2
#define Tdim 2048
#define Edim 1024
#define Hdim 16
#define Ddim 64
#define Vdim 32000
#define BT   (Bdim * Tdim)   // 4096

// ---------------- scratch (static device globals; no allocation) -------------
__device__ float g_q[BT * Edim];
__device__ float g_k[BT * Edim];
__device__ float g_v[BT * Edim];
__device__ float g_rowloss[BT];

// bf16 hi/lo split operands for tensor-core GEMMs
__device__ __nv_bfloat16 g_xh[BT * Edim], g_xl[BT * Edim];
__device__ __nv_bfloat16 g_oh[BT * Edim], g_ol[BT * Edim];
__device__ __nv_bfloat16 g_wqh[Edim * Edim], g_wql[Edim * Edim];
__device__ __nv_bfloat16 g_wkh[Edim * Edim], g_wkl[Edim * Edim];
__device__ __nv_bfloat16 g_wvh[Edim * Edim], g_wvl[Edim * Edim];
__device__ __nv_bfloat16 g_woh[Vdim * Edim], g_wol[Vdim * Edim];

// ---------------- small helpers ----------------------------------------------
__device__ __forceinline__ void split1(float v, __nv_bfloat16& h, __nv_bfloat16& l) {
    h = __float2bfloat16(v);
    l = __float2bfloat16(v - __bfloat162float(h));   // residual exact in fp32
}

__device__ __forceinline__ uint32_t smem_u32(const void* p) {
    uint32_t a;
    asm("{ .reg .u64 t; cvta.to.shared.u64 t, %1; cvt.u32.u64 %0, t; }" : "=r"(a) : "l"(p));
    return a;
}

__device__ __forceinline__ void ldsm4(uint32_t* r, uint32_t addr) {
    asm volatile("ldmatrix.sync.aligned.m8n8.x4.shared.b16 {%0,%1,%2,%3}, [%4];"
                 : "=r"(r[0]), "=r"(r[1]), "=r"(r[2]), "=r"(r[3]) : "r"(addr));
}

__device__ __forceinline__ void mma16816(float* c, const uint32_t* a, const uint32_t* b) {
    asm volatile("mma.sync.aligned.m16n8k16.row.col.f32.bf16.bf16.f32 "
                 "{%0,%1,%2,%3}, {%4,%5,%6,%7}, {%8,%9}, {%0,%1,%2,%3};"
                 : "+f"(c[0]), "+f"(c[1]), "+f"(c[2]), "+f"(c[3])
                 : "r"(a[0]), "r"(a[1]), "r"(a[2]), "r"(a[3]), "r"(b[0]), "r"(b[1]));
}

#define CP_ASYNC16(s, g) asm volatile("cp.async.cg.shared.global [%0], [%1], 16;" :: "r"(s), "l"(g))
#define CP_COMMIT()      asm volatile("cp.async.commit_group;")
#define CP_WAIT1()       asm volatile("cp.async.wait_group 1;")
#define CP_WAIT0()       asm volatile("cp.async.wait_group 0;")

// ---------------- embed: write hi/lo bf16 of tok_table[tok] + pos_emb[t] -----
__global__ void embed_kernel(const int* __restrict__ tokens,
                             const float* __restrict__ tok_table,
                             const float* __restrict__ pos_emb) {
    int rowi = blockIdx.x;
    int t = rowi & (Tdim - 1);
    int tok = tokens[rowi];
    const float4* tt = (const float4*)(tok_table + (size_t)tok * Edim);
    const float4* pp = (const float4*)(pos_emb + (size_t)t * Edim);
    int i = threadIdx.x;                // 256 threads x float4
    float4 a = tt[i], b = pp[i];
    float v[4] = {a.x + b.x, a.y + b.y, a.z + b.z, a.w + b.w};
    __nv_bfloat16 h[4], l[4];
#pragma unroll
    for (int j = 0; j < 4; j++) split1(v[j], h[j], l[j]);
    size_t off = (size_t)rowi * Edim + i * 4;
    *(uint2*)(g_xh + off) = *(uint2*)h;
    *(uint2*)(g_xl + off) = *(uint2*)l;
}

// ---------------- fp32 -> bf16 hi/lo split (weights) --------------------------
__global__ __launch_bounds__(256)
void split_kernel(const float* __restrict__ src, __nv_bfloat16* __restrict__ hi,
                  __nv_bfloat16* __restrict__ lo, int n4) {
    int i = blockIdx.x * 256 + threadIdx.x;
    int stride = gridDim.x * 256;
    const float4* s4 = (const float4*)src;
    for (; i < n4; i += stride) {
        float4 v = s4[i];
        float f[4] = {v.x, v.y, v.z, v.w};
        __nv_bfloat16 h[4], l[4];
#pragma unroll
        for (int j = 0; j < 4; j++) split1(f[j], h[j], l[j]);
        *(uint2*)(hi + (size_t)i * 4) = *(uint2*)h;
        *(uint2*)(lo + (size_t)i * 4) = *(uint2*)l;
    }
}

// ---------------- HMMA split-bf16 GEMM: C = A*B^T + bias ---------------------
// A[M,K], B[N,K] bf16 (hi,lo), K-major. CTA tile 128x128, BK=32, 8 warps,
// warp tile 64x32. 3-term split into fp32 mma accumulators.
// 3-stage cp.async pipeline, ONE __syncthreads per k-chunk.
#define KPB 80                      // smem bytes per row (32 bf16 + 8 pad)
#define MT_BYTES (128 * KPB)        // 10240 per matrix tile
#define TG_STAGE (4 * MT_BYTES)     // Ah, Al, Bh, Bl
#define TG_NSTAGE 3
#define TG_SMEM  (TG_NSTAGE * TG_STAGE)   // 122880 B

__global__ __launch_bounds__(256, 1)
void tgemm_kernel(const __nv_bfloat16* __restrict__ Ah, const __nv_bfloat16* __restrict__ Al,
                  const __nv_bfloat16* __restrict__ Bh, const __nv_bfloat16* __restrict__ Bl,
                  const float* __restrict__ bias, float* __restrict__ C,
                  int M, int N, int K, int swG) {
    extern __shared__ char smem[];
    const uint32_t sbase = smem_u32(smem);
    const int tid = threadIdx.x;
    const int lane = tid & 31, wid = tid >> 5;

    // tile coords with L2 swizzle (groups of swG m-tiles)
    const int nt_n = N >> 7;
    const int per = swG * nt_n;
    const int grp = blockIdx.x / per, rem = blockIdx.x % per;
    const int bm = (grp * swG + rem % swG) << 7;
    const int bn = (rem / swG) << 7;

    // ---- global->smem mapping: 512 16B chunks per matrix, 2 per thread ------
    const int c0 = tid, c1 = tid + 256;
    const int r0c = c0 >> 2, q0 = c0 & 3;      // row, 16B-seg
    const int r1c = c1 >> 2, q1 = c1 & 3;
    const uint32_t so00 = r0c * KPB + q0 * 16;
    const uint32_t so01 = r1c * KPB + q1 * 16;
    const char* gAh = (const char*)Ah;  const char* gAl = (const char*)Al;
    const char* gBh = (const char*)Bh;  const char* gBl = (const char*)Bl;
    const size_t ga0 = ((size_t)(bm + r0c) * K + q0 * 8) * 2;
    const size_t ga1 = ((size_t)(bm + r1c) * K + q1 * 8) * 2;
    const size_t gb0 = ((size_t)(bn + r0c) * K + q0 * 8) * 2;
    const size_t gb1 = ((size_t)(bn + r1c) * K + q1 * 8) * 2;

    const int NK = K >> 5;   // BK = 32

#define LOAD_STAGE(buf, kc)                                                      \
    do {                                                                         \
        const uint32_t b_ = sbase + (buf) * TG_STAGE;                            \
        const size_t kb_ = (size_t)(kc) * 64;                                    \
        CP_ASYNC16(b_ + 0 * MT_BYTES + so00, gAh + ga0 + kb_);                   \
        CP_ASYNC16(b_ + 0 * MT_BYTES + so01, gAh + ga1 + kb_);                   \
        CP_ASYNC16(b_ + 1 * MT_BYTES + so00, gAl + ga0 + kb_);                   \
        CP_ASYNC16(b_ + 1 * MT_BYTES + so01, gAl + ga1 + kb_);                   \
        CP_ASYNC16(b_ + 2 * MT_BYTES + so00, gBh + gb0 + kb_);                   \
        CP_ASYNC16(b_ + 2 * MT_BYTES + so01, gBh + gb1 + kb_);                   \
        CP_ASYNC16(b_ + 3 * MT_BYTES + so00, gBl + gb0 + kb_);                   \
        CP_ASYNC16(b_ + 3 * MT_BYTES + so01, gBl + gb1 + kb_);                   \
    } while (0)

    // ---- warp compute mapping ----
    const int wm = (wid >> 2) * 64;        // 0 or 64
    const int wn = (wid & 3) * 32;         // 0,32,64,96
    const uint32_t arow = (lane & 7) | (((lane >> 3) & 1) << 3);
    const uint32_t akoff = (lane >> 4) * 16;
    const uint32_t brow = (lane & 7) + ((lane >> 4) << 3);
    const uint32_t bkoff = ((lane >> 3) & 1) * 16;

    float acc[4][4][4];
#pragma unroll
    for (int i = 0; i < 4; i++)
#pragma unroll
        for (int j = 0; j < 4; j++)
#pragma unroll
            for (int r = 0; r < 4; r++) acc[i][j][r] = 0.f;

    // prologue: stages 0 and 1 in flight
    LOAD_STAGE(0, 0);
    CP_COMMIT();
    if (NK > 1) { LOAD_STAGE(1, 1); }
    CP_COMMIT();

    int cur = 0;
    for (int kc = 0; kc < NK; kc++) {
        if (kc == NK - 1) { CP_WAIT0(); } else { CP_WAIT1(); }
        __syncthreads();
        // prefetch stage kc+2 into buffer (cur+2)%3 — safe: every warp past this
        // barrier has finished compute(kc-1), the last reader of that buffer.
        if (kc + 2 < NK) {
            int nb = cur + 2; if (nb >= TG_NSTAGE) nb -= TG_NSTAGE;
            LOAD_STAGE(nb, kc + 2);
            CP_COMMIT();
        }

        const uint32_t bufA = sbase + cur * TG_STAGE;
        const uint32_t bufB = bufA + 2 * MT_BYTES;
#pragma unroll
        for (int ks = 0; ks < 2; ks++) {
            const uint32_t koff = ks * 32;
            uint32_t ah[4][4], al[4][4];
#pragma unroll
            for (int i = 0; i < 4; i++) {
                uint32_t ad = bufA + (wm + i * 16 + arow) * KPB + koff + akoff;
                ldsm4(ah[i], ad);
                ldsm4(al[i], ad + MT_BYTES);
            }
            uint32_t bh[4][2], bl[4][2];
#pragma unroll
            for (int jj = 0; jj < 2; jj++) {
                uint32_t bd = bufB + (wn + jj * 16 + brow) * KPB + koff + bkoff;
                uint32_t t[4];
                ldsm4(t, bd);
                bh[2 * jj][0] = t[0]; bh[2 * jj][1] = t[1];
                bh[2 * jj + 1][0] = t[2]; bh[2 * jj + 1][1] = t[3];
                ldsm4(t, bd + MT_BYTES);
                bl[2 * jj][0] = t[0]; bl[2 * jj][1] = t[1];
                bl[2 * jj + 1][0] = t[2]; bl[2 * jj + 1][1] = t[3];
            }
#pragma unroll
            for (int i = 0; i < 4; i++)
#pragma unroll
                for (int j = 0; j < 4; j++) {
                    mma16816(acc[i][j], ah[i], bh[j]);
                    mma16816(acc[i][j], ah[i], bl[j]);
                    mma16816(acc[i][j], al[i], bh[j]);
                }
        }
        cur++; if (cur == TG_NSTAGE) cur = 0;
    }

    // ---- epilogue: add bias, write fp32 C ----
    const int er = bm + wm + (lane >> 2);
    const int ec = bn + wn + 2 * (lane & 3);
#pragma unroll
    for (int i = 0; i < 4; i++) {
#pragma unroll
        for (int j = 0; j < 4; j++) {
            const int row = er + i * 16, col = ec + j * 8;
            const float b0 = bias[col], b1 = bias[col + 1];
            float2 v0 = {acc[i][j][0] + b0, acc[i][j][1] + b1};
            float2 v1 = {acc[i][j][2] + b0, acc[i][j][3] + b1};
            *(float2*)(C + (size_t)row * N + col) = v0;
            *(float2*)(C + (size_t)(row + 8) * N + col) = v1;
        }
    }
#undef LOAD_STAGE
}

// ---------------- flash attention (causal + exact reference quirks) ----------
#define ATTN_SMEM_FLOATS (3 * 64 * 68 + 64 * 65)
__global__ __launch_bounds__(256)
void attn_kernel(const float* __restrict__ Q, const float* __restrict__ Kg,
                 const float* __restrict__ Vg) {
    extern __shared__ float sm[];
    float* Qs = sm;                 // 64 x 68
    float* Ks = sm + 64 * 68;
    float* Vs = sm + 2 * 64 * 68;
    float* Ps = sm + 3 * 64 * 68;   // 64 x 65

    const int tid = threadIdx.x;
    const int row = tid >> 2, q4 = tid & 3;
    const int b = blockIdx.y >> 4, h = blockIdx.y & 15;
    const int t0 = blockIdx.x << 6;
    const int lc16 = q4 << 4;
    const size_t base = ((size_t)(b * Tdim + t0 + row)) * Edim + h * 64;

    {
        const float4* src = (const float4*)(Q + base + lc16);
        float4* dst = (float4*)(Qs + row * 68 + lc16);
        dst[0] = src[0]; dst[1] = src[1]; dst[2] = src[2]; dst[3] = src[3];
    }
    __syncthreads();
    float4 qreg[16];
#pragma unroll
    for (int i = 0; i < 16; i++) qreg[i] = ((const float4*)(Qs + row * 68))[i];

    const int tg = t0 + row;
    float m_run = -INFINITY, l_run = 0.f;
    float4 o0 = {0, 0, 0, 0}, o1 = o0, o2 = o0, o3 = o0;

    const int ntiles = blockIdx.x + 1;
    for (int tile = 0; tile < ntiles; tile++) {
        const int s0 = tile << 6;
        __syncthreads();
        {
            size_t kb = ((size_t)(b * Tdim + s0 + row)) * Edim + h * 64 + lc16;
            const float4* ks = (const float4*)(Kg + kb);
            const float4* vs = (const float4*)(Vg + kb);
            float4* kd = (float4*)(Ks + row * 68 + lc16);
            float4* vd = (float4*)(Vs + row * 68 + lc16);
            kd[0] = ks[0]; kd[1] = ks[1]; kd[2] = ks[2]; kd[3] = ks[3];
            vd[0] = vs[0]; vd[1] = vs[1]; vd[2] = vs[2]; vd[3] = vs[3];
        }
        __syncthreads();

        float sc[16];
#pragma unroll
        for (int jj = 0; jj < 16; jj++) {
            const int s = (jj << 2) | q4;
            const float4* kr = (const float4*)(Ks + s * 68);
            float acc = 0.f;
#pragma unroll
            for (int d = 0; d < 16; d++) {
                float4 kv = kr[d];
                acc = fmaf(qreg[d].x, kv.x, acc);
                acc = fmaf(qreg[d].y, kv.y, acc);
                acc = fmaf(qreg[d].z, kv.z, acc);
                acc = fmaf(qreg[d].w, kv.w, acc);
            }
            const int sg = s0 + s;
            sc[jj] = (sg <= tg && acc != 0.0f) ? acc : -INFINITY;
        }

        float mloc = sc[0];
#pragma unroll
        for (int jj = 1; jj < 16; jj++) mloc = fmaxf(mloc, sc[jj]);
        mloc = fmaxf(mloc, __shfl_xor_sync(0xffffffffu, mloc, 1));
        mloc = fmaxf(mloc, __shfl_xor_sync(0xffffffffu, mloc, 2));
        const float m_new = fmaxf(m_run, mloc);
        const float corr = __expf(m_run - m_new);
        float psum = 0.f;
#pragma unroll
        for (int jj = 0; jj < 16; jj++) {
            float p = __expf(sc[jj] - m_new);
            psum += p;
            Ps[row * 65 + ((jj << 2) | q4)] = p;
        }
        psum += __shfl_xor_sync(0xffffffffu, psum, 1);
        psum += __shfl_xor_sync(0xffffffffu, psum, 2);
        l_run = l_run * corr + psum;
        m_run = m_new;
        o0.x *= corr; o0.y *= corr; o0.z *= corr; o0.w *= corr;
        o1.x *= corr; o1.y *= corr; o1.z *= corr; o1.w *= corr;
        o2.x *= corr; o2.y *= corr; o2.z *= corr; o2.w *= corr;
        o3.x *= corr; o3.y *= corr; o3.z *= corr; o3.w *= corr;
        __syncwarp();

        const float* prow = Ps + row * 65;
#pragma unroll 8
        for (int s = 0; s < 64; s++) {
            const float pv = prow[s];
            const float4* vr = (const float4*)(Vs + s * 68 + lc16);
            float4 v0 = vr[0], v1 = vr[1], v2 = vr[2], v3 = vr[3];
            o0.x = fmaf(pv, v0.x, o0.x); o0.y = fmaf(pv, v0.y, o0.y);
            o0.z = fmaf(pv, v0.z, o0.z); o0.w = fmaf(pv, v0.w, o0.w);
            o1.x = fmaf(pv, v1.x, o1.x); o1.y = fmaf(pv, v1.y, o1.y);
            o1.z = fmaf(pv, v1.z, o1.z); o1.w = fmaf(pv, v1.w, o1.w);
            o2.x = fmaf(pv, v2.x, o2.x); o2.y = fmaf(pv, v2.y, o2.y);
            o2.z = fmaf(pv, v2.z, o2.z); o2.w = fmaf(pv, v2.w, o2.w);
            o3.x = fmaf(pv, v3.x, o3.x); o3.y = fmaf(pv, v3.y, o3.y);
            o3.z = fmaf(pv, v3.z, o3.z); o3.w = fmaf(pv, v3.w, o3.w);
        }
    }

    const float inv = 1.0f / (l_run * 8.0f);   // normalize, THEN /sqrt(D)
    float vals[16] = {o0.x * inv, o0.y * inv, o0.z * inv, o0.w * inv,
                      o1.x * inv, o1.y * inv, o1.z * inv, o1.w * inv,
                      o2.x * inv, o2.y * inv, o2.z * inv, o2.w * inv,
                      o3.x * inv, o3.y * inv, o3.z * inv, o3.w * inv};
    __nv_bfloat16 hs[16], ls[16];
#pragma unroll
    for (int i = 0; i < 16; i++) split1(vals[i], hs[i], ls[i]);
    *(uint4*)(g_oh + base + lc16)     = ((uint4*)hs)[0];
    *(uint4*)(g_oh + base + lc16 + 8) = ((uint4*)hs)[1];
    *(uint4*)(g_ol + base + lc16)     = ((uint4*)ls)[0];
    *(uint4*)(g_ol + base + lc16 + 8) = ((uint4*)ls)[1];
}

// ---------------- per-row NLL: ONE pass (online softmax) ---------------------
__global__ __launch_bounds__(256)
void loss_row_kernel(const float* __restrict__ logits,
                     const int* __restrict__ targets,
                     float* __restrict__ rowloss) {
    __shared__ float redm[256];
    __shared__ float reds[256];
    const int row = blockIdx.x, tid = threadIdx.x;
    const float* lr = logits + (size_t)row * Vdim;
    const float4* lr4 = (const float4*)lr;

    float m = -INFINITY, s = 0.f;
    for (int i = tid; i < Vdim / 4; i += 256) {
        float4 v = lr4[i];
        float m4 = fmaxf(fmaxf(v.x, v.y), fmaxf(v.z, v.w));
        float mn = fmaxf(m, m4);
        s = s * __expf(m - mn)
          + __expf(v.x - mn) + __expf(v.y - mn) + __expf(v.z - mn) + __expf(v.w - mn);
        m = mn;
    }
    redm[tid] = m; reds[tid] = s; __syncthreads();
    for (int k = 128; k > 0; k >>= 1) {
        if (tid < k) {
            float m1 = redm[tid], m2 = redm[tid + k];
            float mn = fmaxf(m1, m2);
            reds[tid] = reds[tid] * __expf(m1 - mn) + reds[tid + k] * __expf(m2 - mn);
            redm[tid] = mn;
        }
        __syncthreads();
    }
    if (tid == 0)
        rowloss[row] = (redm[0] + __logf(reds[0])) - lr[targets[row]];
}

__global__ __launch_bounds__(256)
void loss_reduce_kernel(const float* __restrict__ rowloss, float* __restrict__ out) {
    __shared__ float red[256];
    const int tid = threadIdx.x;
    float s = 0.f;
    for (int i = tid; i < BT; i += 256) s += rowloss[i];
    red[tid] = s; __syncthreads();
    for (int k = 128; k > 0; k >>= 1) {
        if (tid < k) red[tid] += red[tid + k];
        __syncthreads();
    }
    if (tid == 0) *out = red[0] / (float)BT;
}

// ---------------- launch ------------------------------------------------------
extern "C" void kernel_launch(void* const* d_in, const int* in_sizes, int n_in,
                              void* d_out, int out_size) {
    const int*   tokens    = (const int*)d_in[0];
    const int*   targets   = (const int*)d_in[1];
    const float* tok_table = (const float*)d_in[2];
    const float* pos_emb   = (const float*)d_in[3];
    const float* Wq        = (const float*)d_in[4];
    const float* bq        = (const float*)d_in[5];
    const float* Wk        = (const float*)d_in[6];
    const float* bk        = (const float*)d_in[7];
    const float* Wv        = (const float*)d_in[8];
    const float* bv        = (const float*)d_in[9];
    const float* Wo        = (const float*)d_in[10];
    const float* bo        = (const float*)d_in[11];
    float* out = (float*)d_out;

    float *pq, *pk, *pv, *prl;
    cudaGetSymbolAddress((void**)&pq,  g_q);
    cudaGetSymbolAddress((void**)&pk,  g_k);
    cudaGetSymbolAddress((void**)&pv,  g_v);
    cudaGetSymbolAddress((void**)&prl, g_rowloss);

    __nv_bfloat16 *pxh, *pxl, *poh, *pol;
    __nv_bfloat16 *pwqh, *pwql, *pwkh, *pwkl, *pwvh, *pwvl, *pwoh, *pwol;
    cudaGetSymbolAddress((void**)&pxh, g_xh);  cudaGetSymbolAddress((void**)&pxl, g_xl);
    cudaGetSymbolAddress((void**)&poh, g_oh);  cudaGetSymbolAddress((void**)&pol, g_ol);
    cudaGetSymbolAddress((void**)&pwqh, g_wqh); cudaGetSymbolAddress((void**)&pwql, g_wql);
    cudaGetSymbolAddress((void**)&pwkh, g_wkh); cudaGetSymbolAddress((void**)&pwkl, g_wkl);
    cudaGetSymbolAddress((void**)&pwvh, g_wvh); cudaGetSymbolAddress((void**)&pwvl, g_wvl);
    cudaGetSymbolAddress((void**)&pwoh, g_woh); cudaGetSymbolAddress((void**)&pwol, g_wol);

    cudaFuncSetAttribute(tgemm_kernel, cudaFuncAttributeMaxDynamicSharedMemorySize, TG_SMEM);
    cudaFuncSetAttribute(attn_kernel, cudaFuncAttributeMaxDynamicSharedMemorySize,
                         ATTN_SMEM_FLOATS * (int)sizeof(float));

    // embed (writes xh/xl directly) + weight splits
    embed_kernel<<<BT, 256>>>(tokens, tok_table, pos_emb);
    split_kernel<<<512, 256>>>(Wq, pwqh, pwql, Edim * Edim / 4);
    split_kernel<<<512, 256>>>(Wk, pwkh, pwkl, Edim * Edim / 4);
    split_kernel<<<512, 256>>>(Wv, pwvh, pwvl, Edim * Edim / 4);
    split_kernel<<<2048, 256>>>(Wo, pwoh, pwol, Vdim * Edim / 4);

    // QKV projections: [4096,1024] = x @ W^T + b
    const int gq = (BT / 128) * (Edim / 128);
    tgemm_kernel<<<gq, 256, TG_SMEM>>>(pxh, pxl, pwqh, pwql, bq, pq, BT, Edim, Edim, 8);
    tgemm_kernel<<<gq, 256, TG_SMEM>>>(pxh, pxl, pwkh, pwkl, bk, pk, BT, Edim, Edim, 8);
    tgemm_kernel<<<gq, 256, TG_SMEM>>>(pxh, pxl, pwvh, pwvl, bv, pv, BT, Edim, Edim, 8);

    // attention (writes oh/ol directly)
    attn_kernel<<<dim3(Tdim / 64, Bdim * Hdim), 256,
                  ATTN_SMEM_FLOATS * sizeof(float)>>>(pq, pk, pv);

    // logits: [4096,32000] = o @ Wo^T + bo
    const int gl = (BT / 128) * (Vdim / 128);
    tgemm_kernel<<<gl, 256, TG_SMEM>>>(poh, pol, pwoh, pwol, bo, out, BT, Vdim, Edim, 8);

    if ((long long)out_size > (long long)BT * Vdim) {
        loss_row_kernel<<<BT, 256>>>(out, targets, prl);
        loss_reduce_kernel<<<1, 256>>>(prl, out + (size_t)BT * Vdim);
    }
}

// round 14
// speedup vs baseline: 2.0165x; 1.1134x over previous
#include <cuda_runtime.h>
#include <cuda_fp16.h>
#include <math.h>
#include <stdint.h>

#define Bdim 2
#define Tdim 2048
#define Edim 1024
#define Hdim 16
#define Ddim 64
#define Vdim 32000
#define BT   (Bdim * Tdim)   // 4096

// ---------------- scratch (static device globals; no allocation) -------------
__device__ float g_q[BT * Edim];
__device__ float g_k[BT * Edim];
__device__ float g_v[BT * Edim];
__device__ float g_rowloss[BT];

// fp16 hi/lo split operands for tensor-core GEMMs
__device__ __half g_xh[BT * Edim], g_xl[BT * Edim];
__device__ __half g_oh[BT * Edim], g_ol[BT * Edim];
__device__ __half g_wqh[Edim * Edim], g_wql[Edim * Edim];
__device__ __half g_wkh[Edim * Edim], g_wkl[Edim * Edim];
__device__ __half g_wvh[Edim * Edim], g_wvl[Edim * Edim];
__device__ __half g_woh[Vdim * Edim];          // logits uses single-fp16 W

// ---------------- small helpers ----------------------------------------------
__device__ __forceinline__ void split1h(float v, __half& h, __half& l) {
    h = __float2half(v);
    l = __float2half(v - __half2float(h));   // residual (exact diff in fp32)
}

__device__ __forceinline__ uint32_t smem_u32(const void* p) {
    uint32_t a;
    asm("{ .reg .u64 t; cvta.to.shared.u64 t, %1; cvt.u32.u64 %0, t; }" : "=r"(a) : "l"(p));
    return a;
}

__device__ __forceinline__ void ldsm4(uint32_t* r, uint32_t addr) {
    asm volatile("ldmatrix.sync.aligned.m8n8.x4.shared.b16 {%0,%1,%2,%3}, [%4];"
                 : "=r"(r[0]), "=r"(r[1]), "=r"(r[2]), "=r"(r[3]) : "r"(addr));
}

__device__ __forceinline__ void mma16816(float* c, const uint32_t* a, const uint32_t* b) {
    asm volatile("mma.sync.aligned.m16n8k16.row.col.f32.f16.f16.f32 "
                 "{%0,%1,%2,%3}, {%4,%5,%6,%7}, {%8,%9}, {%0,%1,%2,%3};"
                 : "+f"(c[0]), "+f"(c[1]), "+f"(c[2]), "+f"(c[3])
                 : "r"(a[0]), "r"(a[1]), "r"(a[2]), "r"(a[3]), "r"(b[0]), "r"(b[1]));
}

#define CP_ASYNC16(s, g) asm volatile("cp.async.cg.shared.global [%0], [%1], 16;" :: "r"(s), "l"(g))
#define CP_COMMIT()      asm volatile("cp.async.commit_group;")
#define CP_WAIT1()       asm volatile("cp.async.wait_group 1;")
#define CP_WAIT0()       asm volatile("cp.async.wait_group 0;")

// ---------------- merged weight split: Wq/Wk/Wv -> fp16 hi+lo, Wo -> fp16 ----
#define WSPLIT_N4  (Edim * Edim / 4)          // 262144 float4 per small W
#define WO_N4      (Vdim * Edim / 4)          // 8192000 float4
#define SPLIT_TOT  (3 * WSPLIT_N4 + WO_N4)    // 8978432
__global__ __launch_bounds__(256)
void split_all_kernel(const float* __restrict__ Wq, const float* __restrict__ Wk,
                      const float* __restrict__ Wv, const float* __restrict__ Wo) {
    int idx = blockIdx.x * 256 + threadIdx.x;
    if (idx >= SPLIT_TOT) return;
    if (idx < 3 * WSPLIT_N4) {
        int which = idx / WSPLIT_N4;
        int i = idx - which * WSPLIT_N4;
        const float* src = which == 0 ? Wq : which == 1 ? Wk : Wv;
        __half* hi = which == 0 ? g_wqh : which == 1 ? g_wkh : g_wvh;
        __half* lo = which == 0 ? g_wql : which == 1 ? g_wkl : g_wvl;
        float4 v = ((const float4*)src)[i];
        float f[4] = {v.x, v.y, v.z, v.w};
        __half h[4], l[4];
#pragma unroll
        for (int j = 0; j < 4; j++) split1h(f[j], h[j], l[j]);
        *(uint2*)(hi + (size_t)i * 4) = *(uint2*)h;
        *(uint2*)(lo + (size_t)i * 4) = *(uint2*)l;
    } else {
        int i = idx - 3 * WSPLIT_N4;
        float4 v = ((const float4*)Wo)[i];
        __half h[4] = {__float2half(v.x), __float2half(v.y),
                       __float2half(v.z), __float2half(v.w)};
        *(uint2*)(g_woh + (size_t)i * 4) = *(uint2*)h;
    }
}

// ---------------- embed: x = tok_table[tok] + pos_emb[t] -> fp16 hi/lo -------
__global__ void embed_kernel(const int* __restrict__ tokens,
                             const float* __restrict__ tok_table,
                             const float* __restrict__ pos_emb) {
    int rowi = blockIdx.x;
    int t = rowi & (Tdim - 1);
    int tok = tokens[rowi];
    const float4* tt = (const float4*)(tok_table + (size_t)tok * Edim);
    const float4* pp = (const float4*)(pos_emb + (size_t)t * Edim);
    int i = threadIdx.x;                // 256 threads x float4
    float4 a = tt[i], b = pp[i];
    float v[4] = {a.x + b.x, a.y + b.y, a.z + b.z, a.w + b.w};
    __half h[4], l[4];
#pragma unroll
    for (int j = 0; j < 4; j++) split1h(v[j], h[j], l[j]);
    size_t off = (size_t)rowi * Edim + i * 4;
    *(uint2*)(g_xh + off) = *(uint2*)h;
    *(uint2*)(g_xl + off) = *(uint2*)l;
}

// ---------------- shared GEMM constants --------------------------------------
#define KPB 80                      // smem bytes per row (32 fp16 + 8 pad)
#define MT_BYTES (128 * KPB)        // 10240 per matrix tile
#define TG_NSTAGE 3

// =========== 3-term fp16 GEMM (QKV): C = (Ah+Al)*(Bh+Bl)^T + bias ============
// terms kept: ah*bh + ah*bl + al*bh
#define TG3_STAGE (4 * MT_BYTES)
#define TG3_SMEM  (TG_NSTAGE * TG3_STAGE)   // 122880 B

__global__ __launch_bounds__(256, 1)
void tgemm3_kernel(const __half* __restrict__ Ah, const __half* __restrict__ Al,
                   const __half* __restrict__ Bh, const __half* __restrict__ Bl,
                   const float* __restrict__ bias, float* __restrict__ C,
                   int M, int N, int K, int swG) {
    extern __shared__ char smem[];
    const uint32_t sbase = smem_u32(smem);
    const int tid = threadIdx.x;
    const int lane = tid & 31, wid = tid >> 5;

    const int nt_n = N >> 7;
    const int per = swG * nt_n;
    const int grp = blockIdx.x / per, rem = blockIdx.x % per;
    const int bm = (grp * swG + rem % swG) << 7;
    const int bn = (rem / swG) << 7;

    const int r0c = tid >> 2, q0 = tid & 3;
    const int r1c = (tid + 256) >> 2, q1 = tid & 3;
    const uint32_t so00 = r0c * KPB + q0 * 16;
    const uint32_t so01 = r1c * KPB + q1 * 16;
    const char* gAh = (const char*)Ah;  const char* gAl = (const char*)Al;
    const char* gBh = (const char*)Bh;  const char* gBl = (const char*)Bl;
    const size_t ga0 = ((size_t)(bm + r0c) * K + q0 * 8) * 2;
    const size_t ga1 = ((size_t)(bm + r1c) * K + q1 * 8) * 2;
    const size_t gb0 = ((size_t)(bn + r0c) * K + q0 * 8) * 2;
    const size_t gb1 = ((size_t)(bn + r1c) * K + q1 * 8) * 2;

    const int NK = K >> 5;

#define LOAD_STAGE3(buf, kc)                                                     \
    do {                                                                         \
        const uint32_t b_ = sbase + (buf) * TG3_STAGE;                           \
        const size_t kb_ = (size_t)(kc) * 64;                                    \
        CP_ASYNC16(b_ + 0 * MT_BYTES + so00, gAh + ga0 + kb_);                   \
        CP_ASYNC16(b_ + 0 * MT_BYTES + so01, gAh + ga1 + kb_);                   \
        CP_ASYNC16(b_ + 1 * MT_BYTES + so00, gAl + ga0 + kb_);                   \
        CP_ASYNC16(b_ + 1 * MT_BYTES + so01, gAl + ga1 + kb_);                   \
        CP_ASYNC16(b_ + 2 * MT_BYTES + so00, gBh + gb0 + kb_);                   \
        CP_ASYNC16(b_ + 2 * MT_BYTES + so01, gBh + gb1 + kb_);                   \
        CP_ASYNC16(b_ + 3 * MT_BYTES + so00, gBl + gb0 + kb_);                   \
        CP_ASYNC16(b_ + 3 * MT_BYTES + so01, gBl + gb1 + kb_);                   \
    } while (0)

    const int wm = (wid >> 2) * 64;
    const int wn = (wid & 3) * 32;
    const uint32_t arow = (lane & 7) | (((lane >> 3) & 1) << 3);
    const uint32_t akoff = (lane >> 4) * 16;
    const uint32_t brow = (lane & 7) + ((lane >> 4) << 3);
    const uint32_t bkoff = ((lane >> 3) & 1) * 16;

    float acc[4][4][4];
#pragma unroll
    for (int i = 0; i < 4; i++)
#pragma unroll
        for (int j = 0; j < 4; j++)
#pragma unroll
            for (int r = 0; r < 4; r++) acc[i][j][r] = 0.f;

    LOAD_STAGE3(0, 0);
    CP_COMMIT();
    if (NK > 1) { LOAD_STAGE3(1, 1); }
    CP_COMMIT();

    int cur = 0;
    for (int kc = 0; kc < NK; kc++) {
        if (kc == NK - 1) { CP_WAIT0(); } else { CP_WAIT1(); }
        __syncthreads();
        if (kc + 2 < NK) {
            int nb = cur + 2; if (nb >= TG_NSTAGE) nb -= TG_NSTAGE;
            LOAD_STAGE3(nb, kc + 2);
            CP_COMMIT();
        }

        const uint32_t bufA = sbase + cur * TG3_STAGE;
        const uint32_t bufB = bufA + 2 * MT_BYTES;
#pragma unroll
        for (int ks = 0; ks < 2; ks++) {
            const uint32_t koff = ks * 32;
            uint32_t ah[4][4], al[4][4];
#pragma unroll
            for (int i = 0; i < 4; i++) {
                uint32_t ad = bufA + (wm + i * 16 + arow) * KPB + koff + akoff;
                ldsm4(ah[i], ad);
                ldsm4(al[i], ad + MT_BYTES);
            }
            uint32_t bh[4][2], bl[4][2];
#pragma unroll
            for (int jj = 0; jj < 2; jj++) {
                uint32_t bd = bufB + (wn + jj * 16 + brow) * KPB + koff + bkoff;
                uint32_t t[4];
                ldsm4(t, bd);
                bh[2 * jj][0] = t[0]; bh[2 * jj][1] = t[1];
                bh[2 * jj + 1][0] = t[2]; bh[2 * jj + 1][1] = t[3];
                ldsm4(t, bd + MT_BYTES);
                bl[2 * jj][0] = t[0]; bl[2 * jj][1] = t[1];
                bl[2 * jj + 1][0] = t[2]; bl[2 * jj + 1][1] = t[3];
            }
#pragma unroll
            for (int i = 0; i < 4; i++)
#pragma unroll
                for (int j = 0; j < 4; j++) {
                    mma16816(acc[i][j], ah[i], bh[j]);
                    mma16816(acc[i][j], ah[i], bl[j]);
                    mma16816(acc[i][j], al[i], bh[j]);
                }
        }
        cur++; if (cur == TG_NSTAGE) cur = 0;
    }

    const int er = bm + wm + (lane >> 2);
    const int ec = bn + wn + 2 * (lane & 3);
#pragma unroll
    for (int i = 0; i < 4; i++) {
#pragma unroll
        for (int j = 0; j < 4; j++) {
            const int row = er + i * 16, col = ec + j * 8;
            const float b0 = bias[col], b1 = bias[col + 1];
            float2 v0 = {acc[i][j][0] + b0, acc[i][j][1] + b1};
            float2 v1 = {acc[i][j][2] + b0, acc[i][j][3] + b1};
            *(float2*)(C + (size_t)row * N + col) = v0;
            *(float2*)(C + (size_t)(row + 8) * N + col) = v1;
        }
    }
#undef LOAD_STAGE3
}

// ====== 2-term fp16 GEMM (logits): C = (Ah+Al)*Bh^T + bias ==================
#define TG2_STAGE (3 * MT_BYTES)
#define TG2_SMEM  (TG_NSTAGE * TG2_STAGE)   // 92160 B

__global__ __launch_bounds__(256, 1)
void tgemm2_kernel(const __half* __restrict__ Ah, const __half* __restrict__ Al,
                   const __half* __restrict__ Bh,
                   const float* __restrict__ bias, float* __restrict__ C,
                   int M, int N, int K, int swG) {
    extern __shared__ char smem[];
    const uint32_t sbase = smem_u32(smem);
    const int tid = threadIdx.x;
    const int lane = tid & 31, wid = tid >> 5;

    const int nt_n = N >> 7;
    const int per = swG * nt_n;
    const int grp = blockIdx.x / per, rem = blockIdx.x % per;
    const int bm = (grp * swG + rem % swG) << 7;
    const int bn = (rem / swG) << 7;

    const int r0c = tid >> 2, q0 = tid & 3;
    const int r1c = (tid + 256) >> 2, q1 = tid & 3;
    const uint32_t so00 = r0c * KPB + q0 * 16;
    const uint32_t so01 = r1c * KPB + q1 * 16;
    const char* gAh = (const char*)Ah;  const char* gAl = (const char*)Al;
    const char* gBh = (const char*)Bh;
    const size_t ga0 = ((size_t)(bm + r0c) * K + q0 * 8) * 2;
    const size_t ga1 = ((size_t)(bm + r1c) * K + q1 * 8) * 2;
    const size_t gb0 = ((size_t)(bn + r0c) * K + q0 * 8) * 2;
    const size_t gb1 = ((size_t)(bn + r1c) * K + q1 * 8) * 2;

    const int NK = K >> 5;

#define LOAD_STAGE2(buf, kc)                                                     \
    do {                                                                         \
        const uint32_t b_ = sbase + (buf) * TG2_STAGE;                           \
        const size_t kb_ = (size_t)(kc) * 64;                                    \
        CP_ASYNC16(b_ + 0 * MT_BYTES + so00, gAh + ga0 + kb_);                   \
        CP_ASYNC16(b_ + 0 * MT_BYTES + so01, gAh + ga1 + kb_);                   \
        CP_ASYNC16(b_ + 1 * MT_BYTES + so00, gAl + ga0 + kb_);                   \
        CP_ASYNC16(b_ + 1 * MT_BYTES + so01, gAl + ga1 + kb_);                   \
        CP_ASYNC16(b_ + 2 * MT_BYTES + so00, gBh + gb0 + kb_);                   \
        CP_ASYNC16(b_ + 2 * MT_BYTES + so01, gBh + gb1 + kb_);                   \
    } while (0)

    const int wm = (wid >> 2) * 64;
    const int wn = (wid & 3) * 32;
    const uint32_t arow = (lane & 7) | (((lane >> 3) & 1) << 3);
    const uint32_t akoff = (lane >> 4) * 16;
    const uint32_t brow = (lane & 7) + ((lane >> 4) << 3);
    const uint32_t bkoff = ((lane >> 3) & 1) * 16;

    float acc[4][4][4];
#pragma unroll
    for (int i = 0; i < 4; i++)
#pragma unroll
        for (int j = 0; j < 4; j++)
#pragma unroll
            for (int r = 0; r < 4; r++) acc[i][j][r] = 0.f;

    LOAD_STAGE2(0, 0);
    CP_COMMIT();
    if (NK > 1) { LOAD_STAGE2(1, 1); }
    CP_COMMIT();

    int cur = 0;
    for (int kc = 0; kc < NK; kc++) {
        if (kc == NK - 1) { CP_WAIT0(); } else { CP_WAIT1(); }
        __syncthreads();
        if (kc + 2 < NK) {
            int nb = cur + 2; if (nb >= TG_NSTAGE) nb -= TG_NSTAGE;
            LOAD_STAGE2(nb, kc + 2);
            CP_COMMIT();
        }

        const uint32_t bufA = sbase + cur * TG2_STAGE;
        const uint32_t bufB = bufA + 2 * MT_BYTES;
#pragma unroll
        for (int ks = 0; ks < 2; ks++) {
            const uint32_t koff = ks * 32;
            uint32_t ah[4][4], al[4][4];
#pragma unroll
            for (int i = 0; i < 4; i++) {
                uint32_t ad = bufA + (wm + i * 16 + arow) * KPB + koff + akoff;
                ldsm4(ah[i], ad);
                ldsm4(al[i], ad + MT_BYTES);
            }
            uint32_t bh[4][2];
#pragma unroll
            for (int jj = 0; jj < 2; jj++) {
                uint32_t bd = bufB + (wn + jj * 16 + brow) * KPB + koff + bkoff;
                uint32_t t[4];
                ldsm4(t, bd);
                bh[2 * jj][0] = t[0]; bh[2 * jj][1] = t[1];
                bh[2 * jj + 1][0] = t[2]; bh[2 * jj + 1][1] = t[3];
            }
#pragma unroll
            for (int i = 0; i < 4; i++)
#pragma unroll
                for (int j = 0; j < 4; j++) {
                    mma16816(acc[i][j], ah[i], bh[j]);
                    mma16816(acc[i][j], al[i], bh[j]);
                }
        }
        cur++; if (cur == TG_NSTAGE) cur = 0;
    }

    const int er = bm + wm + (lane >> 2);
    const int ec = bn + wn + 2 * (lane & 3);
#pragma unroll
    for (int i = 0; i < 4; i++) {
#pragma unroll
        for (int j = 0; j < 4; j++) {
            const int row = er + i * 16, col = ec + j * 8;
            const float b0 = bias[col], b1 = bias[col + 1];
            float2 v0 = {acc[i][j][0] + b0, acc[i][j][1] + b1};
            float2 v1 = {acc[i][j][2] + b0, acc[i][j][3] + b1};
            *(float2*)(C + (size_t)row * N + col) = v0;
            *(float2*)(C + (size_t)(row + 8) * N + col) = v1;
        }
    }
#undef LOAD_STAGE2
}

// ---------------- flash attention (causal + exact reference quirks) ----------
#define ATTN_SMEM_FLOATS (3 * 64 * 68 + 64 * 65)
__global__ __launch_bounds__(256)
void attn_kernel(const float* __restrict__ Q, const float* __restrict__ Kg,
                 const float* __restrict__ Vg) {
    extern __shared__ float sm[];
    float* Qs = sm;                 // 64 x 68
    float* Ks = sm + 64 * 68;
    float* Vs = sm + 2 * 64 * 68;
    float* Ps = sm + 3 * 64 * 68;   // 64 x 65

    const int tid = threadIdx.x;
    const int row = tid >> 2, q4 = tid & 3;
    const int b = blockIdx.y >> 4, h = blockIdx.y & 15;
    const int t0 = blockIdx.x << 6;
    const int lc16 = q4 << 4;
    const size_t base = ((size_t)(b * Tdim + t0 + row)) * Edim + h * 64;

    {
        const float4* src = (const float4*)(Q + base + lc16);
        float4* dst = (float4*)(Qs + row * 68 + lc16);
        dst[0] = src[0]; dst[1] = src[1]; dst[2] = src[2]; dst[3] = src[3];
    }
    __syncthreads();
    float4 qreg[16];
#pragma unroll
    for (int i = 0; i < 16; i++) qreg[i] = ((const float4*)(Qs + row * 68))[i];

    const int tg = t0 + row;
    float m_run = -INFINITY, l_run = 0.f;
    float4 o0 = {0, 0, 0, 0}, o1 = o0, o2 = o0, o3 = o0;

    const int ntiles = blockIdx.x + 1;
    for (int tile = 0; tile < ntiles; tile++) {
        const int s0 = tile << 6;
        __syncthreads();
        {
            size_t kb = ((size_t)(b * Tdim + s0 + row)) * Edim + h * 64 + lc16;
            const float4* ks = (const float4*)(Kg + kb);
            const float4* vs = (const float4*)(Vg + kb);
            float4* kd = (float4*)(Ks + row * 68 + lc16);
            float4* vd = (float4*)(Vs + row * 68 + lc16);
            kd[0] = ks[0]; kd[1] = ks[1]; kd[2] = ks[2]; kd[3] = ks[3];
            vd[0] = vs[0]; vd[1] = vs[1]; vd[2] = vs[2]; vd[3] = vs[3];
        }
        __syncthreads();

        float sc[16];
#pragma unroll
        for (int jj = 0; jj < 16; jj++) {
            const int s = (jj << 2) | q4;
            const float4* kr = (const float4*)(Ks + s * 68);
            float acc = 0.f;
#pragma unroll
            for (int d = 0; d < 16; d++) {
                float4 kv = kr[d];
                acc = fmaf(qreg[d].x, kv.x, acc);
                acc = fmaf(qreg[d].y, kv.y, acc);
                acc = fmaf(qreg[d].z, kv.z, acc);
                acc = fmaf(qreg[d].w, kv.w, acc);
            }
            const int sg = s0 + s;
            // reference quirk: masked-out OR exactly-zero scores -> -inf
            sc[jj] = (sg <= tg && acc != 0.0f) ? acc : -INFINITY;
        }

        float mloc = sc[0];
#pragma unroll
        for (int jj = 1; jj < 16; jj++) mloc = fmaxf(mloc, sc[jj]);
        mloc = fmaxf(mloc, __shfl_xor_sync(0xffffffffu, mloc, 1));
        mloc = fmaxf(mloc, __shfl_xor_sync(0xffffffffu, mloc, 2));
        const float m_new = fmaxf(m_run, mloc);
        const float corr = __expf(m_run - m_new);
        float psum = 0.f;
#pragma unroll
        for (int jj = 0; jj < 16; jj++) {
            float p = __expf(sc[jj] - m_new);
            psum += p;
            Ps[row * 65 + ((jj << 2) | q4)] = p;
        }
        psum += __shfl_xor_sync(0xffffffffu, psum, 1);
        psum += __shfl_xor_sync(0xffffffffu, psum, 2);
        l_run = l_run * corr + psum;
        m_run = m_new;
        o0.x *= corr; o0.y *= corr; o0.z *= corr; o0.w *= corr;
        o1.x *= corr; o1.y *= corr; o1.z *= corr; o1.w *= corr;
        o2.x *= corr; o2.y *= corr; o2.z *= corr; o2.w *= corr;
        o3.x *= corr; o3.y *= corr; o3.z *= corr; o3.w *= corr;
        __syncwarp();

        const float* prow = Ps + row * 65;
#pragma unroll 8
        for (int s = 0; s < 64; s++) {
            const float pv = prow[s];
            const float4* vr = (const float4*)(Vs + s * 68 + lc16);
            float4 v0 = vr[0], v1 = vr[1], v2 = vr[2], v3 = vr[3];
            o0.x = fmaf(pv, v0.x, o0.x); o0.y = fmaf(pv, v0.y, o0.y);
            o0.z = fmaf(pv, v0.z, o0.z); o0.w = fmaf(pv, v0.w, o0.w);
            o1.x = fmaf(pv, v1.x, o1.x); o1.y = fmaf(pv, v1.y, o1.y);
            o1.z = fmaf(pv, v1.z, o1.z); o1.w = fmaf(pv, v1.w, o1.w);
            o2.x = fmaf(pv, v2.x, o2.x); o2.y = fmaf(pv, v2.y, o2.y);
            o2.z = fmaf(pv, v2.z, o2.z); o2.w = fmaf(pv, v2.w, o2.w);
            o3.x = fmaf(pv, v3.x, o3.x); o3.y = fmaf(pv, v3.y, o3.y);
            o3.z = fmaf(pv, v3.z, o3.z); o3.w = fmaf(pv, v3.w, o3.w);
        }
    }

    const float inv = 1.0f / (l_run * 8.0f);   // normalize, THEN /sqrt(D)
    float vals[16] = {o0.x * inv, o0.y * inv, o0.z * inv, o0.w * inv,
                      o1.x * inv, o1.y * inv, o1.z * inv, o1.w * inv,
                      o2.x * inv, o2.y * inv, o2.z * inv, o2.w * inv,
                      o3.x * inv, o3.y * inv, o3.z * inv, o3.w * inv};
    __half hs[16], ls[16];
#pragma unroll
    for (int i = 0; i < 16; i++) split1h(vals[i], hs[i], ls[i]);
    *(uint4*)(g_oh + base + lc16)     = ((uint4*)hs)[0];
    *(uint4*)(g_oh + base + lc16 + 8) = ((uint4*)hs)[1];
    *(uint4*)(g_ol + base + lc16)     = ((uint4*)ls)[0];
    *(uint4*)(g_ol + base + lc16 + 8) = ((uint4*)ls)[1];
}

// ---------------- per-row NLL: ONE pass (online softmax) ---------------------
__global__ __launch_bounds__(256)
void loss_row_kernel(const float* __restrict__ logits,
                     const int* __restrict__ targets,
                     float* __restrict__ rowloss) {
    __shared__ float redm[256];
    __shared__ float reds[256];
    const int row = blockIdx.x, tid = threadIdx.x;
    const float* lr = logits + (size_t)row * Vdim;
    const float4* lr4 = (const float4*)lr;

    float m = -INFINITY, s = 0.f;
    for (int i = tid; i < Vdim / 4; i += 256) {
        float4 v = lr4[i];
        float m4 = fmaxf(fmaxf(v.x, v.y), fmaxf(v.z, v.w));
        float mn = fmaxf(m, m4);
        s = s * __expf(m - mn)
          + __expf(v.x - mn) + __expf(v.y - mn) + __expf(v.z - mn) + __expf(v.w - mn);
        m = mn;
    }
    redm[tid] = m; reds[tid] = s; __syncthreads();
    for (int k = 128; k > 0; k >>= 1) {
        if (tid < k) {
            float m1 = redm[tid], m2 = redm[tid + k];
            float mn = fmaxf(m1, m2);
            reds[tid] = reds[tid] * __expf(m1 - mn) + reds[tid + k] * __expf(m2 - mn);
            redm[tid] = mn;
        }
        __syncthreads();
    }
    if (tid == 0)
        rowloss[row] = (redm[0] + __logf(reds[0])) - lr[targets[row]];
}

__global__ __launch_bounds__(256)
void loss_reduce_kernel(const float* __restrict__ rowloss, float* __restrict__ out) {
    __shared__ float red[256];
    const int tid = threadIdx.x;
    float s = 0.f;
    for (int i = tid; i < BT; i += 256) s += rowloss[i];
    red[tid] = s; __syncthreads();
    for (int k = 128; k > 0; k >>= 1) {
        if (tid < k) red[tid] += red[tid + k];
        __syncthreads();
    }
    if (tid == 0) *out = red[0] / (float)BT;
}

// ---------------- launch ------------------------------------------------------
extern "C" void kernel_launch(void* const* d_in, const int* in_sizes, int n_in,
                              void* d_out, int out_size) {
    const int*   tokens    = (const int*)d_in[0];
    const int*   targets   = (const int*)d_in[1];
    const float* tok_table = (const float*)d_in[2];
    const float* pos_emb   = (const float*)d_in[3];
    const float* Wq        = (const float*)d_in[4];
    const float* bq        = (const float*)d_in[5];
    const float* Wk        = (const float*)d_in[6];
    const float* bk        = (const float*)d_in[7];
    const float* Wv        = (const float*)d_in[8];
    const float* bv        = (const float*)d_in[9];
    const float* Wo        = (const float*)d_in[10];
    const float* bo        = (const float*)d_in[11];
    float* out = (float*)d_out;

    float *pq, *pk, *pv, *prl;
    cudaGetSymbolAddress((void**)&pq,  g_q);
    cudaGetSymbolAddress((void**)&pk,  g_k);
    cudaGetSymbolAddress((void**)&pv,  g_v);
    cudaGetSymbolAddress((void**)&prl, g_rowloss);

    __half *pxh, *pxl, *poh, *pol;
    __half *pwqh, *pwql, *pwkh, *pwkl, *pwvh, *pwvl, *pwoh;
    cudaGetSymbolAddress((void**)&pxh, g_xh);  cudaGetSymbolAddress((void**)&pxl, g_xl);
    cudaGetSymbolAddress((void**)&poh, g_oh);  cudaGetSymbolAddress((void**)&pol, g_ol);
    cudaGetSymbolAddress((void**)&pwqh, g_wqh); cudaGetSymbolAddress((void**)&pwql, g_wql);
    cudaGetSymbolAddress((void**)&pwkh, g_wkh); cudaGetSymbolAddress((void**)&pwkl, g_wkl);
    cudaGetSymbolAddress((void**)&pwvh, g_wvh); cudaGetSymbolAddress((void**)&pwvl, g_wvl);
    cudaGetSymbolAddress((void**)&pwoh, g_woh);

    cudaFuncSetAttribute(tgemm3_kernel, cudaFuncAttributeMaxDynamicSharedMemorySize, TG3_SMEM);
    cudaFuncSetAttribute(tgemm2_kernel, cudaFuncAttributeMaxDynamicSharedMemorySize, TG2_SMEM);
    cudaFuncSetAttribute(attn_kernel, cudaFuncAttributeMaxDynamicSharedMemorySize,
                         ATTN_SMEM_FLOATS * (int)sizeof(float));

    // launch #0: all weight splits in one kernel
    split_all_kernel<<<(SPLIT_TOT + 255) / 256, 256>>>(Wq, Wk, Wv, Wo);
    // launch #1: embed (writes xh/xl)
    embed_kernel<<<BT, 256>>>(tokens, tok_table, pos_emb);

    // launches #2-#4: QKV projections (fp16 3-term)
    const int gq = (BT / 128) * (Edim / 128);
    tgemm3_kernel<<<gq, 256, TG3_SMEM>>>(pxh, pxl, pwqh, pwql, bq, pq, BT, Edim, Edim, 8);
    tgemm3_kernel<<<gq, 256, TG3_SMEM>>>(pxh, pxl, pwkh, pwkl, bk, pk, BT, Edim, Edim, 8);
    tgemm3_kernel<<<gq, 256, TG3_SMEM>>>(pxh, pxl, pwvh, pwvl, bv, pv, BT, Edim, Edim, 8);

    // launch #5: attention (writes oh/ol fp16)
    attn_kernel<<<dim3(Tdim / 64, Bdim * Hdim), 256,
                  ATTN_SMEM_FLOATS * sizeof(float)>>>(pq, pk, pv);

    // launch #6: logits (fp16 2-term)
    const int gl = (BT / 128) * (Vdim / 128);
    tgemm2_kernel<<<gl, 256, TG2_SMEM>>>(poh, pol, pwoh, bo, out, BT, Vdim, Edim, 8);

    if ((long long)out_size > (long long)BT * Vdim) {
        loss_row_kernel<<<BT, 256>>>(out, targets, prl);
        loss_reduce_kernel<<<1, 256>>>(prl, out + (size_t)BT * Vdim);
    }
}

// round 15
// speedup vs baseline: 2.2787x; 1.1300x over previous
#include <cuda_runtime.h>
#include <cuda_fp16.h>
#include <math.h>
#include <stdint.h>

#define Bdim 2
#define Tdim 2048
#define Edim 1024
#define Hdim 16
#define Ddim 64
#define Vdim 32000
#define BT   (Bdim * Tdim)   // 4096

// ---------------- scratch (static device globals; no allocation) -------------
__device__ float g_q[BT * Edim];
__device__ float g_k[BT * Edim];
__device__ float g_v[BT * Edim];
__device__ float g_rowloss[BT];

// fp16 hi/lo split operands for tensor-core GEMMs
__device__ __half g_xh[BT * Edim], g_xl[BT * Edim];
__device__ __half g_oh[BT * Edim], g_ol[BT * Edim];
__device__ __half g_wqh[Edim * Edim], g_wql[Edim * Edim];
__device__ __half g_wkh[Edim * Edim], g_wkl[Edim * Edim];
__device__ __half g_wvh[Edim * Edim], g_wvl[Edim * Edim];
__device__ __half g_woh[Vdim * Edim];          // logits uses single-fp16 W

// ---------------- small helpers ----------------------------------------------
__device__ __forceinline__ void split1h(float v, __half& h, __half& l) {
    h = __float2half(v);
    l = __float2half(v - __half2float(h));   // residual (exact diff in fp32)
}

__device__ __forceinline__ uint32_t smem_u32(const void* p) {
    uint32_t a;
    asm("{ .reg .u64 t; cvta.to.shared.u64 t, %1; cvt.u32.u64 %0, t; }" : "=r"(a) : "l"(p));
    return a;
}

__device__ __forceinline__ void ldsm4(uint32_t* r, uint32_t addr) {
    asm volatile("ldmatrix.sync.aligned.m8n8.x4.shared.b16 {%0,%1,%2,%3}, [%4];"
                 : "=r"(r[0]), "=r"(r[1]), "=r"(r[2]), "=r"(r[3]) : "r"(addr));
}

__device__ __forceinline__ void mma16816(float* c, const uint32_t* a, const uint32_t* b) {
    asm volatile("mma.sync.aligned.m16n8k16.row.col.f32.f16.f16.f32 "
                 "{%0,%1,%2,%3}, {%4,%5,%6,%7}, {%8,%9}, {%0,%1,%2,%3};"
                 : "+f"(c[0]), "+f"(c[1]), "+f"(c[2]), "+f"(c[3])
                 : "r"(a[0]), "r"(a[1]), "r"(a[2]), "r"(a[3]), "r"(b[0]), "r"(b[1]));
}

#define CP_ASYNC16(s, g) asm volatile("cp.async.cg.shared.global [%0], [%1], 16;" :: "r"(s), "l"(g))
#define CP_COMMIT()      asm volatile("cp.async.commit_group;")
#define CP_WAIT0()       asm volatile("cp.async.wait_group 0;")

// ---------------- merged weight split: Wq/Wk/Wv -> fp16 hi+lo, Wo -> fp16 ----
#define WSPLIT_N4  (Edim * Edim / 4)          // 262144 float4 per small W
#define WO_N4      (Vdim * Edim / 4)          // 8192000 float4
#define SPLIT_TOT  (3 * WSPLIT_N4 + WO_N4)    // 8978432
__global__ __launch_bounds__(256)
void split_all_kernel(const float* __restrict__ Wq, const float* __restrict__ Wk,
                      const float* __restrict__ Wv, const float* __restrict__ Wo) {
    int idx = blockIdx.x * 256 + threadIdx.x;
    if (idx >= SPLIT_TOT) return;
    if (idx < 3 * WSPLIT_N4) {
        int which = idx / WSPLIT_N4;
        int i = idx - which * WSPLIT_N4;
        const float* src = which == 0 ? Wq : which == 1 ? Wk : Wv;
        __half* hi = which == 0 ? g_wqh : which == 1 ? g_wkh : g_wvh;
        __half* lo = which == 0 ? g_wql : which == 1 ? g_wkl : g_wvl;
        float4 v = ((const float4*)src)[i];
        float f[4] = {v.x, v.y, v.z, v.w};
        __half h[4], l[4];
#pragma unroll
        for (int j = 0; j < 4; j++) split1h(f[j], h[j], l[j]);
        *(uint2*)(hi + (size_t)i * 4) = *(uint2*)h;
        *(uint2*)(lo + (size_t)i * 4) = *(uint2*)l;
    } else {
        int i = idx - 3 * WSPLIT_N4;
        float4 v = ((const float4*)Wo)[i];
        __half h[4] = {__float2half(v.x), __float2half(v.y),
                       __float2half(v.z), __float2half(v.w)};
        *(uint2*)(g_woh + (size_t)i * 4) = *(uint2*)h;
    }
}

// ---------------- embed: x = tok_table[tok] + pos_emb[t] -> fp16 hi/lo -------
__global__ void embed_kernel(const int* __restrict__ tokens,
                             const float* __restrict__ tok_table,
                             const float* __restrict__ pos_emb) {
    int rowi = blockIdx.x;
    int t = rowi & (Tdim - 1);
    int tok = tokens[rowi];
    const float4* tt = (const float4*)(tok_table + (size_t)tok * Edim);
    const float4* pp = (const float4*)(pos_emb + (size_t)t * Edim);
    int i = threadIdx.x;                // 256 threads x float4
    float4 a = tt[i], b = pp[i];
    float v[4] = {a.x + b.x, a.y + b.y, a.z + b.z, a.w + b.w};
    __half h[4], l[4];
#pragma unroll
    for (int j = 0; j < 4; j++) split1h(v[j], h[j], l[j]);
    size_t off = (size_t)rowi * Edim + i * 4;
    *(uint2*)(g_xh + off) = *(uint2*)h;
    *(uint2*)(g_xl + off) = *(uint2*)l;
}

// ---------------- shared GEMM constants --------------------------------------
#define KPB 80                      // smem bytes per row (32 fp16 + 8 pad)
#define MT_BYTES (128 * KPB)        // 10240 per matrix tile
#define TG_NSTAGE 2

// =========== 3-term fp16 GEMM (QKV): C = (Ah+Al)*(Bh+Bl)^T + bias ============
// terms kept: ah*bh + ah*bl + al*bh, issued TERM-MAJOR (16 independent accs
// between reuses of any accumulator -> HMMA latency hidden).
#define TG3_STAGE (4 * MT_BYTES)
#define TG3_SMEM  (TG_NSTAGE * TG3_STAGE)   // 81920 B  (2 CTAs/SM -> 160 KB)

__global__ __launch_bounds__(256, 2)
void tgemm3_kernel(const __half* __restrict__ Ah, const __half* __restrict__ Al,
                   const __half* __restrict__ Bh, const __half* __restrict__ Bl,
                   const float* __restrict__ bias, float* __restrict__ C,
                   int M, int N, int K, int swG) {
    extern __shared__ char smem[];
    const uint32_t sbase = smem_u32(smem);
    const int tid = threadIdx.x;
    const int lane = tid & 31, wid = tid >> 5;

    const int nt_n = N >> 7;
    const int per = swG * nt_n;
    const int grp = blockIdx.x / per, rem = blockIdx.x % per;
    const int bm = (grp * swG + rem % swG) << 7;
    const int bn = (rem / swG) << 7;

    const int r0c = tid >> 2, q0 = tid & 3;
    const int r1c = (tid + 256) >> 2, q1 = tid & 3;
    const uint32_t so00 = r0c * KPB + q0 * 16;
    const uint32_t so01 = r1c * KPB + q1 * 16;
    const char* gAh = (const char*)Ah;  const char* gAl = (const char*)Al;
    const char* gBh = (const char*)Bh;  const char* gBl = (const char*)Bl;
    const size_t ga0 = ((size_t)(bm + r0c) * K + q0 * 8) * 2;
    const size_t ga1 = ((size_t)(bm + r1c) * K + q1 * 8) * 2;
    const size_t gb0 = ((size_t)(bn + r0c) * K + q0 * 8) * 2;
    const size_t gb1 = ((size_t)(bn + r1c) * K + q1 * 8) * 2;

    const int NK = K >> 5;

#define LOAD_STAGE3(buf, kc)                                                     \
    do {                                                                         \
        const uint32_t b_ = sbase + (buf) * TG3_STAGE;                           \
        const size_t kb_ = (size_t)(kc) * 64;                                    \
        CP_ASYNC16(b_ + 0 * MT_BYTES + so00, gAh + ga0 + kb_);                   \
        CP_ASYNC16(b_ + 0 * MT_BYTES + so01, gAh + ga1 + kb_);                   \
        CP_ASYNC16(b_ + 1 * MT_BYTES + so00, gAl + ga0 + kb_);                   \
        CP_ASYNC16(b_ + 1 * MT_BYTES + so01, gAl + ga1 + kb_);                   \
        CP_ASYNC16(b_ + 2 * MT_BYTES + so00, gBh + gb0 + kb_);                   \
        CP_ASYNC16(b_ + 2 * MT_BYTES + so01, gBh + gb1 + kb_);                   \
        CP_ASYNC16(b_ + 3 * MT_BYTES + so00, gBl + gb0 + kb_);                   \
        CP_ASYNC16(b_ + 3 * MT_BYTES + so01, gBl + gb1 + kb_);                   \
    } while (0)

    const int wm = (wid >> 2) * 64;
    const int wn = (wid & 3) * 32;
    const uint32_t arow = (lane & 7) | (((lane >> 3) & 1) << 3);
    const uint32_t akoff = (lane >> 4) * 16;
    const uint32_t brow = (lane & 7) + ((lane >> 4) << 3);
    const uint32_t bkoff = ((lane >> 3) & 1) * 16;

    float acc[4][4][4];
#pragma unroll
    for (int i = 0; i < 4; i++)
#pragma unroll
        for (int j = 0; j < 4; j++)
#pragma unroll
            for (int r = 0; r < 4; r++) acc[i][j][r] = 0.f;

    LOAD_STAGE3(0, 0);
    CP_COMMIT();

    int cur = 0;
    for (int kc = 0; kc < NK; kc++) {
        CP_WAIT0();
        __syncthreads();   // all warps finished compute(kc-1) -> buffer cur^1 free
        const int nxt = cur ^ 1;
        if (kc + 1 < NK) {
            LOAD_STAGE3(nxt, kc + 1);
            CP_COMMIT();
        }

        const uint32_t bufA = sbase + cur * TG3_STAGE;
        const uint32_t bufB = bufA + 2 * MT_BYTES;
#pragma unroll
        for (int ks = 0; ks < 2; ks++) {
            const uint32_t koff = ks * 32;
            uint32_t af[4][4];             // holds ah, later overwritten by al
            uint32_t bf[4][2], bf2[4][2];  // bh, bl
#pragma unroll
            for (int i = 0; i < 4; i++)
                ldsm4(af[i], bufA + (wm + i * 16 + arow) * KPB + koff + akoff);
#pragma unroll
            for (int jj = 0; jj < 2; jj++) {
                uint32_t bd = bufB + (wn + jj * 16 + brow) * KPB + koff + bkoff;
                uint32_t t[4];
                ldsm4(t, bd);
                bf[2 * jj][0] = t[0]; bf[2 * jj][1] = t[1];
                bf[2 * jj + 1][0] = t[2]; bf[2 * jj + 1][1] = t[3];
                ldsm4(t, bd + MT_BYTES);
                bf2[2 * jj][0] = t[0]; bf2[2 * jj][1] = t[1];
                bf2[2 * jj + 1][0] = t[2]; bf2[2 * jj + 1][1] = t[3];
            }
            // term hh: 16 independent accumulators
#pragma unroll
            for (int i = 0; i < 4; i++)
#pragma unroll
                for (int j = 0; j < 4; j++) mma16816(acc[i][j], af[i], bf[j]);
            // term hl
#pragma unroll
            for (int i = 0; i < 4; i++)
#pragma unroll
                for (int j = 0; j < 4; j++) mma16816(acc[i][j], af[i], bf2[j]);
            // load al (overwrite af), term lh
#pragma unroll
            for (int i = 0; i < 4; i++)
                ldsm4(af[i], bufA + MT_BYTES + (wm + i * 16 + arow) * KPB + koff + akoff);
#pragma unroll
            for (int i = 0; i < 4; i++)
#pragma unroll
                for (int j = 0; j < 4; j++) mma16816(acc[i][j], af[i], bf[j]);
        }
        cur = nxt;
    }

    const int er = bm + wm + (lane >> 2);
    const int ec = bn + wn + 2 * (lane & 3);
#pragma unroll
    for (int i = 0; i < 4; i++) {
#pragma unroll
        for (int j = 0; j < 4; j++) {
            const int row = er + i * 16, col = ec + j * 8;
            const float b0 = bias[col], b1 = bias[col + 1];
            float2 v0 = {acc[i][j][0] + b0, acc[i][j][1] + b1};
            float2 v1 = {acc[i][j][2] + b0, acc[i][j][3] + b1};
            *(float2*)(C + (size_t)row * N + col) = v0;
            *(float2*)(C + (size_t)(row + 8) * N + col) = v1;
        }
    }
#undef LOAD_STAGE3
}

// ====== 2-term fp16 GEMM (logits): C = (Ah+Al)*Bh^T + bias ==================
#define TG2_STAGE (3 * MT_BYTES)
#define TG2_SMEM  (TG_NSTAGE * TG2_STAGE)   // 61440 B  (2 CTAs/SM -> 120 KB)

__global__ __launch_bounds__(256, 2)
void tgemm2_kernel(const __half* __restrict__ Ah, const __half* __restrict__ Al,
                   const __half* __restrict__ Bh,
                   const float* __restrict__ bias, float* __restrict__ C,
                   int M, int N, int K, int swG) {
    extern __shared__ char smem[];
    const uint32_t sbase = smem_u32(smem);
    const int tid = threadIdx.x;
    const int lane = tid & 31, wid = tid >> 5;

    const int nt_n = N >> 7;
    const int per = swG * nt_n;
    const int grp = blockIdx.x / per, rem = blockIdx.x % per;
    const int bm = (grp * swG + rem % swG) << 7;
    const int bn = (rem / swG) << 7;

    const int r0c = tid >> 2, q0 = tid & 3;
    const int r1c = (tid + 256) >> 2, q1 = tid & 3;
    const uint32_t so00 = r0c * KPB + q0 * 16;
    const uint32_t so01 = r1c * KPB + q1 * 16;
    const char* gAh = (const char*)Ah;  const char* gAl = (const char*)Al;
    const char* gBh = (const char*)Bh;
    const size_t ga0 = ((size_t)(bm + r0c) * K + q0 * 8) * 2;
    const size_t ga1 = ((size_t)(bm + r1c) * K + q1 * 8) * 2;
    const size_t gb0 = ((size_t)(bn + r0c) * K + q0 * 8) * 2;
    const size_t gb1 = ((size_t)(bn + r1c) * K + q1 * 8) * 2;

    const int NK = K >> 5;

#define LOAD_STAGE2(buf, kc)                                                     \
    do {                                                                         \
        const uint32_t b_ = sbase + (buf) * TG2_STAGE;                           \
        const size_t kb_ = (size_t)(kc) * 64;                                    \
        CP_ASYNC16(b_ + 0 * MT_BYTES + so00, gAh + ga0 + kb_);                   \
        CP_ASYNC16(b_ + 0 * MT_BYTES + so01, gAh + ga1 + kb_);                   \
        CP_ASYNC16(b_ + 1 * MT_BYTES + so00, gAl + ga0 + kb_);                   \
        CP_ASYNC16(b_ + 1 * MT_BYTES + so01, gAl + ga1 + kb_);                   \
        CP_ASYNC16(b_ + 2 * MT_BYTES + so00, gBh + gb0 + kb_);                   \
        CP_ASYNC16(b_ + 2 * MT_BYTES + so01, gBh + gb1 + kb_);                   \
    } while (0)

    const int wm = (wid >> 2) * 64;
    const int wn = (wid & 3) * 32;
    const uint32_t arow = (lane & 7) | (((lane >> 3) & 1) << 3);
    const uint32_t akoff = (lane >> 4) * 16;
    const uint32_t brow = (lane & 7) + ((lane >> 4) << 3);
    const uint32_t bkoff = ((lane >> 3) & 1) * 16;

    float acc[4][4][4];
#pragma unroll
    for (int i = 0; i < 4; i++)
#pragma unroll
        for (int j = 0; j < 4; j++)
#pragma unroll
            for (int r = 0; r < 4; r++) acc[i][j][r] = 0.f;

    LOAD_STAGE2(0, 0);
    CP_COMMIT();

    int cur = 0;
    for (int kc = 0; kc < NK; kc++) {
        CP_WAIT0();
        __syncthreads();
        const int nxt = cur ^ 1;
        if (kc + 1 < NK) {
            LOAD_STAGE2(nxt, kc + 1);
            CP_COMMIT();
        }

        const uint32_t bufA = sbase + cur * TG2_STAGE;
        const uint32_t bufB = bufA + 2 * MT_BYTES;
#pragma unroll
        for (int ks = 0; ks < 2; ks++) {
            const uint32_t koff = ks * 32;
            uint32_t ah[4][4], al[4][4], bf[4][2];
#pragma unroll
            for (int i = 0; i < 4; i++) {
                uint32_t ad = bufA + (wm + i * 16 + arow) * KPB + koff + akoff;
                ldsm4(ah[i], ad);
                ldsm4(al[i], ad + MT_BYTES);
            }
#pragma unroll
            for (int jj = 0; jj < 2; jj++) {
                uint32_t bd = bufB + (wn + jj * 16 + brow) * KPB + koff + bkoff;
                uint32_t t[4];
                ldsm4(t, bd);
                bf[2 * jj][0] = t[0]; bf[2 * jj][1] = t[1];
                bf[2 * jj + 1][0] = t[2]; bf[2 * jj + 1][1] = t[3];
            }
            // term hh
#pragma unroll
            for (int i = 0; i < 4; i++)
#pragma unroll
                for (int j = 0; j < 4; j++) mma16816(acc[i][j], ah[i], bf[j]);
            // term lh
#pragma unroll
            for (int i = 0; i < 4; i++)
#pragma unroll
                for (int j = 0; j < 4; j++) mma16816(acc[i][j], al[i], bf[j]);
        }
        cur = nxt;
    }

    const int er = bm + wm + (lane >> 2);
    const int ec = bn + wn + 2 * (lane & 3);
#pragma unroll
    for (int i = 0; i < 4; i++) {
#pragma unroll
        for (int j = 0; j < 4; j++) {
            const int row = er + i * 16, col = ec + j * 8;
            const float b0 = bias[col], b1 = bias[col + 1];
            float2 v0 = {acc[i][j][0] + b0, acc[i][j][1] + b1};
            float2 v1 = {acc[i][j][2] + b0, acc[i][j][3] + b1};
            *(float2*)(C + (size_t)row * N + col) = v0;
            *(float2*)(C + (size_t)(row + 8) * N + col) = v1;
        }
    }
#undef LOAD_STAGE2
}

// ---------------- flash attention (causal + exact reference quirks) ----------
#define ATTN_SMEM_FLOATS (3 * 64 * 68 + 64 * 65)
__global__ __launch_bounds__(256)
void attn_kernel(const float* __restrict__ Q, const float* __restrict__ Kg,
                 const float* __restrict__ Vg) {
    extern __shared__ float sm[];
    float* Qs = sm;                 // 64 x 68
    float* Ks = sm + 64 * 68;
    float* Vs = sm + 2 * 64 * 68;
    float* Ps = sm + 3 * 64 * 68;   // 64 x 65

    const int tid = threadIdx.x;
    const int row = tid >> 2, q4 = tid & 3;
    const int b = blockIdx.y >> 4, h = blockIdx.y & 15;
    const int t0 = blockIdx.x << 6;
    const int lc16 = q4 << 4;
    const size_t base = ((size_t)(b * Tdim + t0 + row)) * Edim + h * 64;

    {
        const float4* src = (const float4*)(Q + base + lc16);
        float4* dst = (float4*)(Qs + row * 68 + lc16);
        dst[0] = src[0]; dst[1] = src[1]; dst[2] = src[2]; dst[3] = src[3];
    }
    __syncthreads();
    float4 qreg[16];
#pragma unroll
    for (int i = 0; i < 16; i++) qreg[i] = ((const float4*)(Qs + row * 68))[i];

    const int tg = t0 + row;
    float m_run = -INFINITY, l_run = 0.f;
    float4 o0 = {0, 0, 0, 0}, o1 = o0, o2 = o0, o3 = o0;

    const int ntiles = blockIdx.x + 1;
    for (int tile = 0; tile < ntiles; tile++) {
        const int s0 = tile << 6;
        __syncthreads();
        {
            size_t kb = ((size_t)(b * Tdim + s0 + row)) * Edim + h * 64 + lc16;
            const float4* ks = (const float4*)(Kg + kb);
            const float4* vs = (const float4*)(Vg + kb);
            float4* kd = (float4*)(Ks + row * 68 + lc16);
            float4* vd = (float4*)(Vs + row * 68 + lc16);
            kd[0] = ks[0]; kd[1] = ks[1]; kd[2] = ks[2]; kd[3] = ks[3];
            vd[0] = vs[0]; vd[1] = vs[1]; vd[2] = vs[2]; vd[3] = vs[3];
        }
        __syncthreads();

        float sc[16];
#pragma unroll
        for (int jj = 0; jj < 16; jj++) {
            const int s = (jj << 2) | q4;
            const float4* kr = (const float4*)(Ks + s * 68);
            float acc = 0.f;
#pragma unroll
            for (int d = 0; d < 16; d++) {
                float4 kv = kr[d];
                acc = fmaf(qreg[d].x, kv.x, acc);
                acc = fmaf(qreg[d].y, kv.y, acc);
                acc = fmaf(qreg[d].z, kv.z, acc);
                acc = fmaf(qreg[d].w, kv.w, acc);
            }
            const int sg = s0 + s;
            // reference quirk: masked-out OR exactly-zero scores -> -inf
            sc[jj] = (sg <= tg && acc != 0.0f) ? acc : -INFINITY;
        }

        float mloc = sc[0];
#pragma unroll
        for (int jj = 1; jj < 16; jj++) mloc = fmaxf(mloc, sc[jj]);
        mloc = fmaxf(mloc, __shfl_xor_sync(0xffffffffu, mloc, 1));
        mloc = fmaxf(mloc, __shfl_xor_sync(0xffffffffu, mloc, 2));
        const float m_new = fmaxf(m_run, mloc);
        const float corr = __expf(m_run - m_new);
        float psum = 0.f;
#pragma unroll
        for (int jj = 0; jj < 16; jj++) {
            float p = __expf(sc[jj] - m_new);
            psum += p;
            Ps[row * 65 + ((jj << 2) | q4)] = p;
        }
        psum += __shfl_xor_sync(0xffffffffu, psum, 1);
        psum += __shfl_xor_sync(0xffffffffu, psum, 2);
        l_run = l_run * corr + psum;
        m_run = m_new;
        o0.x *= corr; o0.y *= corr; o0.z *= corr; o0.w *= corr;
        o1.x *= corr; o1.y *= corr; o1.z *= corr; o1.w *= corr;
        o2.x *= corr; o2.y *= corr; o2.z *= corr; o2.w *= corr;
        o3.x *= corr; o3.y *= corr; o3.z *= corr; o3.w *= corr;
        __syncwarp();

        const float* prow = Ps + row * 65;
#pragma unroll 8
        for (int s = 0; s < 64; s++) {
            const float pv = prow[s];
            const float4* vr = (const float4*)(Vs + s * 68 + lc16);
            float4 v0 = vr[0], v1 = vr[1], v2 = vr[2], v3 = vr[3];
            o0.x = fmaf(pv, v0.x, o0.x); o0.y = fmaf(pv, v0.y, o0.y);
            o0.z = fmaf(pv, v0.z, o0.z); o0.w = fmaf(pv, v0.w, o0.w);
            o1.x = fmaf(pv, v1.x, o1.x); o1.y = fmaf(pv, v1.y, o1.y);
            o1.z = fmaf(pv, v1.z, o1.z); o1.w = fmaf(pv, v1.w, o1.w);
            o2.x = fmaf(pv, v2.x, o2.x); o2.y = fmaf(pv, v2.y, o2.y);
            o2.z = fmaf(pv, v2.z, o2.z); o2.w = fmaf(pv, v2.w, o2.w);
            o3.x = fmaf(pv, v3.x, o3.x); o3.y = fmaf(pv, v3.y, o3.y);
            o3.z = fmaf(pv, v3.z, o3.z); o3.w = fmaf(pv, v3.w, o3.w);
        }
    }

    const float inv = 1.0f / (l_run * 8.0f);   // normalize, THEN /sqrt(D)
    float vals[16] = {o0.x * inv, o0.y * inv, o0.z * inv, o0.w * inv,
                      o1.x * inv, o1.y * inv, o1.z * inv, o1.w * inv,
                      o2.x * inv, o2.y * inv, o2.z * inv, o2.w * inv,
                      o3.x * inv, o3.y * inv, o3.z * inv, o3.w * inv};
    __half hs[16], ls[16];
#pragma unroll
    for (int i = 0; i < 16; i++) split1h(vals[i], hs[i], ls[i]);
    *(uint4*)(g_oh + base + lc16)     = ((uint4*)hs)[0];
    *(uint4*)(g_oh + base + lc16 + 8) = ((uint4*)hs)[1];
    *(uint4*)(g_ol + base + lc16)     = ((uint4*)ls)[0];
    *(uint4*)(g_ol + base + lc16 + 8) = ((uint4*)ls)[1];
}

// ---------------- per-row NLL: ONE pass (online softmax) ---------------------
__global__ __launch_bounds__(256)
void loss_row_kernel(const float* __restrict__ logits,
                     const int* __restrict__ targets,
                     float* __restrict__ rowloss) {
    __shared__ float redm[256];
    __shared__ float reds[256];
    const int row = blockIdx.x, tid = threadIdx.x;
    const float* lr = logits + (size_t)row * Vdim;
    const float4* lr4 = (const float4*)lr;

    float m = -INFINITY, s = 0.f;
    for (int i = tid; i < Vdim / 4; i += 256) {
        float4 v = lr4[i];
        float m4 = fmaxf(fmaxf(v.x, v.y), fmaxf(v.z, v.w));
        float mn = fmaxf(m, m4);
        s = s * __expf(m - mn)
          + __expf(v.x - mn) + __expf(v.y - mn) + __expf(v.z - mn) + __expf(v.w - mn);
        m = mn;
    }
    redm[tid] = m; reds[tid] = s; __syncthreads();
    for (int k = 128; k > 0; k >>= 1) {
        if (tid < k) {
            float m1 = redm[tid], m2 = redm[tid + k];
            float mn = fmaxf(m1, m2);
            reds[tid] = reds[tid] * __expf(m1 - mn) + reds[tid + k] * __expf(m2 - mn);
            redm[tid] = mn;
        }
        __syncthreads();
    }
    if (tid == 0)
        rowloss[row] = (redm[0] + __logf(reds[0])) - lr[targets[row]];
}

__global__ __launch_bounds__(256)
void loss_reduce_kernel(const float* __restrict__ rowloss, float* __restrict__ out) {
    __shared__ float red[256];
    const int tid = threadIdx.x;
    float s = 0.f;
    for (int i = tid; i < BT; i += 256) s += rowloss[i];
    red[tid] = s; __syncthreads();
    for (int k = 128; k > 0; k >>= 1) {
        if (tid < k) red[tid] += red[tid + k];
        __syncthreads();
    }
    if (tid == 0) *out = red[0] / (float)BT;
}

// ---------------- launch ------------------------------------------------------
extern "C" void kernel_launch(void* const* d_in, const int* in_sizes, int n_in,
                              void* d_out, int out_size) {
    const int*   tokens    = (const int*)d_in[0];
    const int*   targets   = (const int*)d_in[1];
    const float* tok_table = (const float*)d_in[2];
    const float* pos_emb   = (const float*)d_in[3];
    const float* Wq        = (const float*)d_in[4];
    const float* bq        = (const float*)d_in[5];
    const float* Wk        = (const float*)d_in[6];
    const float* bk        = (const float*)d_in[7];
    const float* Wv        = (const float*)d_in[8];
    const float* bv        = (const float*)d_in[9];
    const float* Wo        = (const float*)d_in[10];
    const float* bo        = (const float*)d_in[11];
    float* out = (float*)d_out;

    float *pq, *pk, *pv, *prl;
    cudaGetSymbolAddress((void**)&pq,  g_q);
    cudaGetSymbolAddress((void**)&pk,  g_k);
    cudaGetSymbolAddress((void**)&pv,  g_v);
    cudaGetSymbolAddress((void**)&prl, g_rowloss);

    __half *pxh, *pxl, *poh, *pol;
    __half *pwqh, *pwql, *pwkh, *pwkl, *pwvh, *pwvl, *pwoh;
    cudaGetSymbolAddress((void**)&pxh, g_xh);  cudaGetSymbolAddress((void**)&pxl, g_xl);
    cudaGetSymbolAddress((void**)&poh, g_oh);  cudaGetSymbolAddress((void**)&pol, g_ol);
    cudaGetSymbolAddress((void**)&pwqh, g_wqh); cudaGetSymbolAddress((void**)&pwql, g_wql);
    cudaGetSymbolAddress((void**)&pwkh, g_wkh); cudaGetSymbolAddress((void**)&pwkl, g_wkl);
    cudaGetSymbolAddress((void**)&pwvh, g_wvh); cudaGetSymbolAddress((void**)&pwvl, g_wvl);
    cudaGetSymbolAddress((void**)&pwoh, g_woh);

    cudaFuncSetAttribute(tgemm3_kernel, cudaFuncAttributeMaxDynamicSharedMemorySize, TG3_SMEM);
    cudaFuncSetAttribute(tgemm2_kernel, cudaFuncAttributeMaxDynamicSharedMemorySize, TG2_SMEM);
    cudaFuncSetAttribute(attn_kernel, cudaFuncAttributeMaxDynamicSharedMemorySize,
                         ATTN_SMEM_FLOATS * (int)sizeof(float));

    // launch #0: all weight splits in one kernel
    split_all_kernel<<<(SPLIT_TOT + 255) / 256, 256>>>(Wq, Wk, Wv, Wo);
    // launch #1: embed (writes xh/xl)
    embed_kernel<<<BT, 256>>>(tokens, tok_table, pos_emb);

    // launches #2-#4: QKV projections (fp16 3-term)
    const int gq = (BT / 128) * (Edim / 128);
    tgemm3_kernel<<<gq, 256, TG3_SMEM>>>(pxh, pxl, pwqh, pwql, bq, pq, BT, Edim, Edim, 8);
    tgemm3_kernel<<<gq, 256, TG3_SMEM>>>(pxh, pxl, pwkh, pwkl, bk, pk, BT, Edim, Edim, 8);
    tgemm3_kernel<<<gq, 256, TG3_SMEM>>>(pxh, pxl, pwvh, pwvl, bv, pv, BT, Edim, Edim, 8);

    // launch #5: attention (writes oh/ol fp16)
    attn_kernel<<<dim3(Tdim / 64, Bdim * Hdim), 256,
                  ATTN_SMEM_FLOATS * sizeof(float)>>>(pq, pk, pv);

    // launch #6: logits (fp16 2-term)
    const int gl = (BT / 128) * (Vdim / 128);
    tgemm2_kernel<<<gl, 256, TG2_SMEM>>>(poh, pol, pwoh, bo, out, BT, Vdim, Edim, 8);

    if ((long long)out_size > (long long)BT * Vdim) {
        loss_row_kernel<<<BT, 256>>>(out, targets, prl);
        loss_reduce_kernel<<<1, 256>>>(prl, out + (size_t)BT * Vdim);
    }
}

// round 16
// speedup vs baseline: 4.4583x; 1.9565x over previous
#include <cuda_runtime.h>
#include <cuda_fp16.h>
#include <math.h>
#include <stdint.h>

#define Bdim 2
#define Tdim 2048
#define Edim 1024
#define Hdim 16
#define Ddim 64
#define Vdim 32000
#define BT   (Bdim * Tdim)   // 4096

// ---------------- scratch (static device globals; no allocation) -------------
__device__ float g_rowloss[BT];

// fp16 operands
__device__ __half g_xh[BT * Edim], g_xl[BT * Edim];
__device__ __half g_qh[BT * Edim], g_kh[BT * Edim], g_vh[BT * Edim];
__device__ __half g_oh[BT * Edim], g_ol[BT * Edim];
__device__ __half g_wqh[Edim * Edim], g_wql[Edim * Edim];
__device__ __half g_wkh[Edim * Edim], g_wkl[Edim * Edim];
__device__ __half g_wvh[Edim * Edim], g_wvl[Edim * Edim];
__device__ __half g_woh[Vdim * Edim];          // logits uses single-fp16 W

// ---------------- small helpers ----------------------------------------------
__device__ __forceinline__ void split1h(float v, __half& h, __half& l) {
    h = __float2half(v);
    l = __float2half(v - __half2float(h));   // residual (exact diff in fp32)
}

__device__ __forceinline__ uint32_t smem_u32(const void* p) {
    uint32_t a;
    asm("{ .reg .u64 t; cvta.to.shared.u64 t, %1; cvt.u32.u64 %0, t; }" : "=r"(a) : "l"(p));
    return a;
}

__device__ __forceinline__ void ldsm4(uint32_t* r, uint32_t addr) {
    asm volatile("ldmatrix.sync.aligned.m8n8.x4.shared.b16 {%0,%1,%2,%3}, [%4];"
                 : "=r"(r[0]), "=r"(r[1]), "=r"(r[2]), "=r"(r[3]) : "r"(addr));
}

__device__ __forceinline__ void ldsm4t(uint32_t* r, uint32_t addr) {
    asm volatile("ldmatrix.sync.aligned.m8n8.x4.trans.shared.b16 {%0,%1,%2,%3}, [%4];"
                 : "=r"(r[0]), "=r"(r[1]), "=r"(r[2]), "=r"(r[3]) : "r"(addr));
}

__device__ __forceinline__ void mma16816(float* c, const uint32_t* a, const uint32_t* b) {
    asm volatile("mma.sync.aligned.m16n8k16.row.col.f32.f16.f16.f32 "
                 "{%0,%1,%2,%3}, {%4,%5,%6,%7}, {%8,%9}, {%0,%1,%2,%3};"
                 : "+f"(c[0]), "+f"(c[1]), "+f"(c[2]), "+f"(c[3])
                 : "r"(a[0]), "r"(a[1]), "r"(a[2]), "r"(a[3]), "r"(b[0]), "r"(b[1]));
}

#define CP_ASYNC16(s, g) asm volatile("cp.async.cg.shared.global [%0], [%1], 16;" :: "r"(s), "l"(g))
#define CP_COMMIT()      asm volatile("cp.async.commit_group;")
#define CP_WAIT0()       asm volatile("cp.async.wait_group 0;")

// ---------------- merged weight split: Wq/Wk/Wv -> fp16 hi+lo, Wo -> fp16 ----
#define WSPLIT_N4  (Edim * Edim / 4)
#define WO_N4      (Vdim * Edim / 4)
#define SPLIT_TOT  (3 * WSPLIT_N4 + WO_N4)
__global__ __launch_bounds__(256)
void split_all_kernel(const float* __restrict__ Wq, const float* __restrict__ Wk,
                      const float* __restrict__ Wv, const float* __restrict__ Wo) {
    int idx = blockIdx.x * 256 + threadIdx.x;
    if (idx >= SPLIT_TOT) return;
    if (idx < 3 * WSPLIT_N4) {
        int which = idx / WSPLIT_N4;
        int i = idx - which * WSPLIT_N4;
        const float* src = which == 0 ? Wq : which == 1 ? Wk : Wv;
        __half* hi = which == 0 ? g_wqh : which == 1 ? g_wkh : g_wvh;
        __half* lo = which == 0 ? g_wql : which == 1 ? g_wkl : g_wvl;
        float4 v = ((const float4*)src)[i];
        float f[4] = {v.x, v.y, v.z, v.w};
        __half h[4], l[4];
#pragma unroll
        for (int j = 0; j < 4; j++) split1h(f[j], h[j], l[j]);
        *(uint2*)(hi + (size_t)i * 4) = *(uint2*)h;
        *(uint2*)(lo + (size_t)i * 4) = *(uint2*)l;
    } else {
        int i = idx - 3 * WSPLIT_N4;
        float4 v = ((const float4*)Wo)[i];
        __half h[4] = {__float2half(v.x), __float2half(v.y),
                       __float2half(v.z), __float2half(v.w)};
        *(uint2*)(g_woh + (size_t)i * 4) = *(uint2*)h;
    }
}

// ---------------- embed: x = tok_table[tok] + pos_emb[t] -> fp16 hi/lo -------
__global__ void embed_kernel(const int* __restrict__ tokens,
                             const float* __restrict__ tok_table,
                             const float* __restrict__ pos_emb) {
    int rowi = blockIdx.x;
    int t = rowi & (Tdim - 1);
    int tok = tokens[rowi];
    const float4* tt = (const float4*)(tok_table + (size_t)tok * Edim);
    const float4* pp = (const float4*)(pos_emb + (size_t)t * Edim);
    int i = threadIdx.x;
    float4 a = tt[i], b = pp[i];
    float v[4] = {a.x + b.x, a.y + b.y, a.z + b.z, a.w + b.w};
    __half h[4], l[4];
#pragma unroll
    for (int j = 0; j < 4; j++) split1h(v[j], h[j], l[j]);
    size_t off = (size_t)rowi * Edim + i * 4;
    *(uint2*)(g_xh + off) = *(uint2*)h;
    *(uint2*)(g_xl + off) = *(uint2*)l;
}

// ---------------- shared GEMM constants --------------------------------------
#define KPB 80                      // smem bytes per row (32 fp16 + 8 pad)
#define MT_BYTES (128 * KPB)
#define TG_NSTAGE 2

// =========== 3-term fp16 GEMM (QKV): C(half) = (Ah+Al)*(Bh+Bl)^T + bias ======
#define TG3_STAGE (4 * MT_BYTES)
#define TG3_SMEM  (TG_NSTAGE * TG3_STAGE)   // 81920 B

__global__ __launch_bounds__(256, 2)
void tgemm3_kernel(const __half* __restrict__ Ah, const __half* __restrict__ Al,
                   const __half* __restrict__ Bh, const __half* __restrict__ Bl,
                   const float* __restrict__ bias, __half* __restrict__ C,
                   int M, int N, int K, int swG) {
    extern __shared__ char smem[];
    const uint32_t sbase = smem_u32(smem);
    const int tid = threadIdx.x;
    const int lane = tid & 31, wid = tid >> 5;

    const int nt_n = N >> 7;
    const int per = swG * nt_n;
    const int grp = blockIdx.x / per, rem = blockIdx.x % per;
    const int bm = (grp * swG + rem % swG) << 7;
    const int bn = (rem / swG) << 7;

    const int r0c = tid >> 2, q0 = tid & 3;
    const int r1c = (tid + 256) >> 2, q1 = tid & 3;
    const uint32_t so00 = r0c * KPB + q0 * 16;
    const uint32_t so01 = r1c * KPB + q1 * 16;
    const char* gAh = (const char*)Ah;  const char* gAl = (const char*)Al;
    const char* gBh = (const char*)Bh;  const char* gBl = (const char*)Bl;
    const size_t ga0 = ((size_t)(bm + r0c) * K + q0 * 8) * 2;
    const size_t ga1 = ((size_t)(bm + r1c) * K + q1 * 8) * 2;
    const size_t gb0 = ((size_t)(bn + r0c) * K + q0 * 8) * 2;
    const size_t gb1 = ((size_t)(bn + r1c) * K + q1 * 8) * 2;

    const int NK = K >> 5;

#define LOAD_STAGE3(buf, kc)                                                     \
    do {                                                                         \
        const uint32_t b_ = sbase + (buf) * TG3_STAGE;                           \
        const size_t kb_ = (size_t)(kc) * 64;                                    \
        CP_ASYNC16(b_ + 0 * MT_BYTES + so00, gAh + ga0 + kb_);                   \
        CP_ASYNC16(b_ + 0 * MT_BYTES + so01, gAh + ga1 + kb_);                   \
        CP_ASYNC16(b_ + 1 * MT_BYTES + so00, gAl + ga0 + kb_);                   \
        CP_ASYNC16(b_ + 1 * MT_BYTES + so01, gAl + ga1 + kb_);                   \
        CP_ASYNC16(b_ + 2 * MT_BYTES + so00, gBh + gb0 + kb_);                   \
        CP_ASYNC16(b_ + 2 * MT_BYTES + so01, gBh + gb1 + kb_);                   \
        CP_ASYNC16(b_ + 3 * MT_BYTES + so00, gBl + gb0 + kb_);                   \
        CP_ASYNC16(b_ + 3 * MT_BYTES + so01, gBl + gb1 + kb_);                   \
    } while (0)

    const int wm = (wid >> 2) * 64;
    const int wn = (wid & 3) * 32;
    const uint32_t arow = (lane & 7) | (((lane >> 3) & 1) << 3);
    const uint32_t akoff = (lane >> 4) * 16;
    const uint32_t brow = (lane & 7) + ((lane >> 4) << 3);
    const uint32_t bkoff = ((lane >> 3) & 1) * 16;

    float acc[4][4][4];
#pragma unroll
    for (int i = 0; i < 4; i++)
#pragma unroll
        for (int j = 0; j < 4; j++)
#pragma unroll
            for (int r = 0; r < 4; r++) acc[i][j][r] = 0.f;

    LOAD_STAGE3(0, 0);
    CP_COMMIT();

    int cur = 0;
    for (int kc = 0; kc < NK; kc++) {
        CP_WAIT0();
        __syncthreads();
        const int nxt = cur ^ 1;
        if (kc + 1 < NK) {
            LOAD_STAGE3(nxt, kc + 1);
            CP_COMMIT();
        }

        const uint32_t bufA = sbase + cur * TG3_STAGE;
        const uint32_t bufB = bufA + 2 * MT_BYTES;
#pragma unroll
        for (int ks = 0; ks < 2; ks++) {
            const uint32_t koff = ks * 32;
            uint32_t af[4][4];
            uint32_t bf[4][2], bf2[4][2];
#pragma unroll
            for (int i = 0; i < 4; i++)
                ldsm4(af[i], bufA + (wm + i * 16 + arow) * KPB + koff + akoff);
#pragma unroll
            for (int jj = 0; jj < 2; jj++) {
                uint32_t bd = bufB + (wn + jj * 16 + brow) * KPB + koff + bkoff;
                uint32_t t[4];
                ldsm4(t, bd);
                bf[2 * jj][0] = t[0]; bf[2 * jj][1] = t[1];
                bf[2 * jj + 1][0] = t[2]; bf[2 * jj + 1][1] = t[3];
                ldsm4(t, bd + MT_BYTES);
                bf2[2 * jj][0] = t[0]; bf2[2 * jj][1] = t[1];
                bf2[2 * jj + 1][0] = t[2]; bf2[2 * jj + 1][1] = t[3];
            }
#pragma unroll
            for (int i = 0; i < 4; i++)
#pragma unroll
                for (int j = 0; j < 4; j++) mma16816(acc[i][j], af[i], bf[j]);
#pragma unroll
            for (int i = 0; i < 4; i++)
#pragma unroll
                for (int j = 0; j < 4; j++) mma16816(acc[i][j], af[i], bf2[j]);
#pragma unroll
            for (int i = 0; i < 4; i++)
                ldsm4(af[i], bufA + MT_BYTES + (wm + i * 16 + arow) * KPB + koff + akoff);
#pragma unroll
            for (int i = 0; i < 4; i++)
#pragma unroll
                for (int j = 0; j < 4; j++) mma16816(acc[i][j], af[i], bf[j]);
        }
        cur = nxt;
    }

    // epilogue: add bias, write fp16 C (q/k/v consumed by HMMA attention)
    const int er = bm + wm + (lane >> 2);
    const int ec = bn + wn + 2 * (lane & 3);
#pragma unroll
    for (int i = 0; i < 4; i++) {
#pragma unroll
        for (int j = 0; j < 4; j++) {
            const int row = er + i * 16, col = ec + j * 8;
            const float b0 = bias[col], b1 = bias[col + 1];
            __half2 h0 = __floats2half2_rn(acc[i][j][0] + b0, acc[i][j][1] + b1);
            __half2 h1 = __floats2half2_rn(acc[i][j][2] + b0, acc[i][j][3] + b1);
            *(__half2*)(C + (size_t)row * N + col) = h0;
            *(__half2*)(C + (size_t)(row + 8) * N + col) = h1;
        }
    }
#undef LOAD_STAGE3
}

// ====== 2-term fp16 GEMM (logits): C = (Ah+Al)*Bh^T + bias ==================
#define TG2_STAGE (3 * MT_BYTES)
#define TG2_SMEM  (TG_NSTAGE * TG2_STAGE)

__global__ __launch_bounds__(256, 2)
void tgemm2_kernel(const __half* __restrict__ Ah, const __half* __restrict__ Al,
                   const __half* __restrict__ Bh,
                   const float* __restrict__ bias, float* __restrict__ C,
                   int M, int N, int K, int swG) {
    extern __shared__ char smem[];
    const uint32_t sbase = smem_u32(smem);
    const int tid = threadIdx.x;
    const int lane = tid & 31, wid = tid >> 5;

    const int nt_n = N >> 7;
    const int per = swG * nt_n;
    const int grp = blockIdx.x / per, rem = blockIdx.x % per;
    const int bm = (grp * swG + rem % swG) << 7;
    const int bn = (rem / swG) << 7;

    const int r0c = tid >> 2, q0 = tid & 3;
    const int r1c = (tid + 256) >> 2, q1 = tid & 3;
    const uint32_t so00 = r0c * KPB + q0 * 16;
    const uint32_t so01 = r1c * KPB + q1 * 16;
    const char* gAh = (const char*)Ah;  const char* gAl = (const char*)Al;
    const char* gBh = (const char*)Bh;
    const size_t ga0 = ((size_t)(bm + r0c) * K + q0 * 8) * 2;
    const size_t ga1 = ((size_t)(bm + r1c) * K + q1 * 8) * 2;
    const size_t gb0 = ((size_t)(bn + r0c) * K + q0 * 8) * 2;
    const size_t gb1 = ((size_t)(bn + r1c) * K + q1 * 8) * 2;

    const int NK = K >> 5;

#define LOAD_STAGE2(buf, kc)                                                     \
    do {                                                                         \
        const uint32_t b_ = sbase + (buf) * TG2_STAGE;                           \
        const size_t kb_ = (size_t)(kc) * 64;                                    \
        CP_ASYNC16(b_ + 0 * MT_BYTES + so00, gAh + ga0 + kb_);                   \
        CP_ASYNC16(b_ + 0 * MT_BYTES + so01, gAh + ga1 + kb_);                   \
        CP_ASYNC16(b_ + 1 * MT_BYTES + so00, gAl + ga0 + kb_);                   \
        CP_ASYNC16(b_ + 1 * MT_BYTES + so01, gAl + ga1 + kb_);                   \
        CP_ASYNC16(b_ + 2 * MT_BYTES + so00, gBh + gb0 + kb_);                   \
        CP_ASYNC16(b_ + 2 * MT_BYTES + so01, gBh + gb1 + kb_);                   \
    } while (0)

    const int wm = (wid >> 2) * 64;
    const int wn = (wid & 3) * 32;
    const uint32_t arow = (lane & 7) | (((lane >> 3) & 1) << 3);
    const uint32_t akoff = (lane >> 4) * 16;
    const uint32_t brow = (lane & 7) + ((lane >> 4) << 3);
    const uint32_t bkoff = ((lane >> 3) & 1) * 16;

    float acc[4][4][4];
#pragma unroll
    for (int i = 0; i < 4; i++)
#pragma unroll
        for (int j = 0; j < 4; j++)
#pragma unroll
            for (int r = 0; r < 4; r++) acc[i][j][r] = 0.f;

    LOAD_STAGE2(0, 0);
    CP_COMMIT();

    int cur = 0;
    for (int kc = 0; kc < NK; kc++) {
        CP_WAIT0();
        __syncthreads();
        const int nxt = cur ^ 1;
        if (kc + 1 < NK) {
            LOAD_STAGE2(nxt, kc + 1);
            CP_COMMIT();
        }

        const uint32_t bufA = sbase + cur * TG2_STAGE;
        const uint32_t bufB = bufA + 2 * MT_BYTES;
#pragma unroll
        for (int ks = 0; ks < 2; ks++) {
            const uint32_t koff = ks * 32;
            uint32_t ah[4][4], al[4][4], bf[4][2];
#pragma unroll
            for (int i = 0; i < 4; i++) {
                uint32_t ad = bufA + (wm + i * 16 + arow) * KPB + koff + akoff;
                ldsm4(ah[i], ad);
                ldsm4(al[i], ad + MT_BYTES);
            }
#pragma unroll
            for (int jj = 0; jj < 2; jj++) {
                uint32_t bd = bufB + (wn + jj * 16 + brow) * KPB + koff + bkoff;
                uint32_t t[4];
                ldsm4(t, bd);
                bf[2 * jj][0] = t[0]; bf[2 * jj][1] = t[1];
                bf[2 * jj + 1][0] = t[2]; bf[2 * jj + 1][1] = t[3];
            }
#pragma unroll
            for (int i = 0; i < 4; i++)
#pragma unroll
                for (int j = 0; j < 4; j++) mma16816(acc[i][j], ah[i], bf[j]);
#pragma unroll
            for (int i = 0; i < 4; i++)
#pragma unroll
                for (int j = 0; j < 4; j++) mma16816(acc[i][j], al[i], bf[j]);
        }
        cur = nxt;
    }

    const int er = bm + wm + (lane >> 2);
    const int ec = bn + wn + 2 * (lane & 3);
#pragma unroll
    for (int i = 0; i < 4; i++) {
#pragma unroll
        for (int j = 0; j < 4; j++) {
            const int row = er + i * 16, col = ec + j * 8;
            const float b0 = bias[col], b1 = bias[col + 1];
            float2 v0 = {acc[i][j][0] + b0, acc[i][j][1] + b1};
            float2 v1 = {acc[i][j][2] + b0, acc[i][j][3] + b1};
            *(float2*)(C + (size_t)row * N + col) = v0;
            *(float2*)(C + (size_t)(row + 8) * N + col) = v1;
        }
    }
#undef LOAD_STAGE2
}

// ---------------- HMMA flash attention (causal + exact reference quirks) -----
// 64 q-rows per CTA, 4 warps (16 rows each), BS=64 keys/iter, D=64.
// QK^T and PV on mma.sync fp16; softmax in fp32 on c-frags; FA2 c-frag -> a-frag
// register reuse. Scale 1/sqrt(D) applied AFTER softmax (reference quirk), and
// (masked || score==0) -> -inf quirk preserved.
#define AKPB 144    // smem row: 64 halves + 8 pad = 144 B (4r-bank stride, ldsm conflict-free)

__global__ __launch_bounds__(128)
void attn_h_kernel(const __half* __restrict__ Q, const __half* __restrict__ K,
                   const __half* __restrict__ V) {
    __shared__ __align__(16) char smemraw[3 * 64 * AKPB];
    const uint32_t sQ = smem_u32(smemraw);
    const uint32_t sK = sQ + 64 * AKPB;
    const uint32_t sV = sK + 64 * AKPB;

    const int tid = threadIdx.x, lane = tid & 31, wid = tid >> 5;
    const int bx = gridDim.x - 1 - blockIdx.x;   // long (late) t-tiles first
    const int b = blockIdx.y >> 4, h = blockIdx.y & 15;
    const int t0 = bx << 6;
    const size_t gbase = (size_t)b * Tdim * Edim + h * 64;

    // load Q tile [64 x 64 halves]
#pragma unroll
    for (int i = 0; i < 4; i++) {
        int idx = tid + i * 128;
        int row = idx >> 3, seg = idx & 7;
        *(uint4*)(smemraw + row * AKPB + seg * 16) =
            *(const uint4*)(Q + gbase + (size_t)(t0 + row) * Edim + seg * 8);
    }
    __syncthreads();

    const int wm = wid << 4;
    const uint32_t arow = lane & 15;
    const uint32_t acol = (lane >> 4) * 16;           // bytes
    uint32_t qf[4][4];
#pragma unroll
    for (int kk = 0; kk < 4; kk++)
        ldsm4(qf[kk], sQ + (wm + arow) * AKPB + kk * 32 + acol);

    const uint32_t brow = (lane & 7) + ((lane >> 4) << 3);
    const uint32_t bcol = ((lane >> 3) & 1) * 16;     // bytes

    float of[8][4];
#pragma unroll
    for (int j = 0; j < 8; j++)
#pragma unroll
        for (int r = 0; r < 4; r++) of[j][r] = 0.f;
    float m0 = -INFINITY, m1 = -INFINITY, l0 = 0.f, l1 = 0.f;
    const int r0 = t0 + wm + (lane >> 2);             // global row (low); high = r0+8

    for (int tile = 0; tile <= bx; tile++) {
        const int s0 = tile << 6;
        __syncthreads();                               // K/V buffers free
#pragma unroll
        for (int i = 0; i < 4; i++) {
            int idx = tid + i * 128;
            int row = idx >> 3, seg = idx & 7;
            size_t g = gbase + (size_t)(s0 + row) * Edim + seg * 8;
            *(uint4*)(smemraw + 64 * AKPB + row * AKPB + seg * 16) = *(const uint4*)(K + g);
            *(uint4*)(smemraw + 128 * AKPB + row * AKPB + seg * 16) = *(const uint4*)(V + g);
        }
        __syncthreads();

        // ---- S = Q K^T  (8 n-tiles of 8 keys) ----
        float sf[8][4];
#pragma unroll
        for (int j = 0; j < 8; j++)
#pragma unroll
            for (int r = 0; r < 4; r++) sf[j][r] = 0.f;
#pragma unroll
        for (int kk = 0; kk < 4; kk++) {
#pragma unroll
            for (int j = 0; j < 4; j++) {
                uint32_t t[4];
                ldsm4(t, sK + (j * 16 + brow) * AKPB + kk * 32 + bcol);
                uint32_t b0[2] = {t[0], t[1]};
                uint32_t b1[2] = {t[2], t[3]};
                mma16816(sf[2 * j], qf[kk], b0);
                mma16816(sf[2 * j + 1], qf[kk], b1);
            }
        }

        // ---- mask + ==0 quirk ----
#pragma unroll
        for (int j = 0; j < 8; j++) {
            const int c = s0 + j * 8 + 2 * (lane & 3);
            sf[j][0] = (c     <= r0     && sf[j][0] != 0.f) ? sf[j][0] : -INFINITY;
            sf[j][1] = (c + 1 <= r0     && sf[j][1] != 0.f) ? sf[j][1] : -INFINITY;
            sf[j][2] = (c     <= r0 + 8 && sf[j][2] != 0.f) ? sf[j][2] : -INFINITY;
            sf[j][3] = (c + 1 <= r0 + 8 && sf[j][3] != 0.f) ? sf[j][3] : -INFINITY;
        }

        // ---- online softmax ----
        float mx0 = sf[0][0], mx1 = sf[0][2];
#pragma unroll
        for (int j = 0; j < 8; j++) {
            mx0 = fmaxf(mx0, fmaxf(sf[j][0], sf[j][1]));
            mx1 = fmaxf(mx1, fmaxf(sf[j][2], sf[j][3]));
        }
        mx0 = fmaxf(mx0, __shfl_xor_sync(0xffffffffu, mx0, 1));
        mx0 = fmaxf(mx0, __shfl_xor_sync(0xffffffffu, mx0, 2));
        mx1 = fmaxf(mx1, __shfl_xor_sync(0xffffffffu, mx1, 1));
        mx1 = fmaxf(mx1, __shfl_xor_sync(0xffffffffu, mx1, 2));
        const float mn0 = fmaxf(m0, mx0), mn1 = fmaxf(m1, mx1);
        const float c0 = __expf(m0 - mn0), c1 = __expf(m1 - mn1);
        m0 = mn0; m1 = mn1;

        uint32_t pa[4][4];   // P a-frags per k-step
        float ps0 = 0.f, ps1 = 0.f;
#pragma unroll
        for (int j = 0; j < 8; j++) {
            float p0 = __expf(sf[j][0] - mn0);
            float p1 = __expf(sf[j][1] - mn0);
            float p2 = __expf(sf[j][2] - mn1);
            float p3 = __expf(sf[j][3] - mn1);
            ps0 += p0 + p1; ps1 += p2 + p3;
            __half2 h01 = __floats2half2_rn(p0, p1);
            __half2 h23 = __floats2half2_rn(p2, p3);
            pa[j >> 1][(j & 1) * 2 + 0] = *(uint32_t*)&h01;
            pa[j >> 1][(j & 1) * 2 + 1] = *(uint32_t*)&h23;
        }
        ps0 += __shfl_xor_sync(0xffffffffu, ps0, 1);
        ps0 += __shfl_xor_sync(0xffffffffu, ps0, 2);
        ps1 += __shfl_xor_sync(0xffffffffu, ps1, 1);
        ps1 += __shfl_xor_sync(0xffffffffu, ps1, 2);
        l0 = l0 * c0 + ps0;
        l1 = l1 * c1 + ps1;
#pragma unroll
        for (int j = 0; j < 8; j++) {
            of[j][0] *= c0; of[j][1] *= c0; of[j][2] *= c1; of[j][3] *= c1;
        }

        // ---- O += P V   (V b-frags via ldmatrix.trans; pairing {t0,t2}/{t1,t3}) ----
#pragma unroll
        for (int ks = 0; ks < 4; ks++) {
#pragma unroll
            for (int dj = 0; dj < 4; dj++) {
                uint32_t t[4];
                ldsm4t(t, sV + (ks * 16 + brow) * AKPB + dj * 32 + bcol);
                uint32_t b0[2] = {t[0], t[2]};
                uint32_t b1[2] = {t[1], t[3]};
                mma16816(of[2 * dj], pa[ks], b0);
                mma16816(of[2 * dj + 1], pa[ks], b1);
            }
        }
    }

    // ---- epilogue: normalize, /sqrt(D), split fp16 hi/lo for logits GEMM ----
    const float inv0 = 1.f / (l0 * 8.f), inv1 = 1.f / (l1 * 8.f);
    const size_t rb0 = gbase + (size_t)r0 * Edim;
    const size_t rb1 = rb0 + 8 * Edim;
#pragma unroll
    for (int j = 0; j < 8; j++) {
        const int d = j * 8 + 2 * (lane & 3);
        float v00 = of[j][0] * inv0, v01 = of[j][1] * inv0;
        float v10 = of[j][2] * inv1, v11 = of[j][3] * inv1;
        __half h00, l00, h01, l01, h10, l10, h11, l11;
        split1h(v00, h00, l00); split1h(v01, h01, l01);
        split1h(v10, h10, l10); split1h(v11, h11, l11);
        *(__half2*)(g_oh + rb0 + d) = __halves2half2(h00, h01);
        *(__half2*)(g_ol + rb0 + d) = __halves2half2(l00, l01);
        *(__half2*)(g_oh + rb1 + d) = __halves2half2(h10, h11);
        *(__half2*)(g_ol + rb1 + d) = __halves2half2(l10, l11);
    }
}

// ---------------- per-row NLL: ONE pass (online softmax) ---------------------
__global__ __launch_bounds__(256)
void loss_row_kernel(const float* __restrict__ logits,
                     const int* __restrict__ targets,
                     float* __restrict__ rowloss) {
    __shared__ float redm[256];
    __shared__ float reds[256];
    const int row = blockIdx.x, tid = threadIdx.x;
    const float* lr = logits + (size_t)row * Vdim;
    const float4* lr4 = (const float4*)lr;

    float m = -INFINITY, s = 0.f;
    for (int i = tid; i < Vdim / 4; i += 256) {
        float4 v = lr4[i];
        float m4 = fmaxf(fmaxf(v.x, v.y), fmaxf(v.z, v.w));
        float mn = fmaxf(m, m4);
        s = s * __expf(m - mn)
          + __expf(v.x - mn) + __expf(v.y - mn) + __expf(v.z - mn) + __expf(v.w - mn);
        m = mn;
    }
    redm[tid] = m; reds[tid] = s; __syncthreads();
    for (int k = 128; k > 0; k >>= 1) {
        if (tid < k) {
            float m1 = redm[tid], m2 = redm[tid + k];
            float mn = fmaxf(m1, m2);
            reds[tid] = reds[tid] * __expf(m1 - mn) + reds[tid + k] * __expf(m2 - mn);
            redm[tid] = mn;
        }
        __syncthreads();
    }
    if (tid == 0)
        rowloss[row] = (redm[0] + __logf(reds[0])) - lr[targets[row]];
}

__global__ __launch_bounds__(256)
void loss_reduce_kernel(const float* __restrict__ rowloss, float* __restrict__ out) {
    __shared__ float red[256];
    const int tid = threadIdx.x;
    float s = 0.f;
    for (int i = tid; i < BT; i += 256) s += rowloss[i];
    red[tid] = s; __syncthreads();
    for (int k = 128; k > 0; k >>= 1) {
        if (tid < k) red[tid] += red[tid + k];
        __syncthreads();
    }
    if (tid == 0) *out = red[0] / (float)BT;
}

// ---------------- launch ------------------------------------------------------
extern "C" void kernel_launch(void* const* d_in, const int* in_sizes, int n_in,
                              void* d_out, int out_size) {
    const int*   tokens    = (const int*)d_in[0];
    const int*   targets   = (const int*)d_in[1];
    const float* tok_table = (const float*)d_in[2];
    const float* pos_emb   = (const float*)d_in[3];
    const float* Wq        = (const float*)d_in[4];
    const float* bq        = (const float*)d_in[5];
    const float* Wk        = (const float*)d_in[6];
    const float* bk        = (const float*)d_in[7];
    const float* Wv        = (const float*)d_in[8];
    const float* bv        = (const float*)d_in[9];
    const float* Wo        = (const float*)d_in[10];
    const float* bo        = (const float*)d_in[11];
    float* out = (float*)d_out;

    float* prl;
    cudaGetSymbolAddress((void**)&prl, g_rowloss);

    __half *pxh, *pxl, *poh, *pol, *pqh, *pkh, *pvh;
    __half *pwqh, *pwql, *pwkh, *pwkl, *pwvh, *pwvl, *pwoh;
    cudaGetSymbolAddress((void**)&pxh, g_xh);  cudaGetSymbolAddress((void**)&pxl, g_xl);
    cudaGetSymbolAddress((void**)&poh, g_oh);  cudaGetSymbolAddress((void**)&pol, g_ol);
    cudaGetSymbolAddress((void**)&pqh, g_qh);
    cudaGetSymbolAddress((void**)&pkh, g_kh);
    cudaGetSymbolAddress((void**)&pvh, g_vh);
    cudaGetSymbolAddress((void**)&pwqh, g_wqh); cudaGetSymbolAddress((void**)&pwql, g_wql);
    cudaGetSymbolAddress((void**)&pwkh, g_wkh); cudaGetSymbolAddress((void**)&pwkl, g_wkl);
    cudaGetSymbolAddress((void**)&pwvh, g_wvh); cudaGetSymbolAddress((void**)&pwvl, g_wvl);
    cudaGetSymbolAddress((void**)&pwoh, g_woh);

    cudaFuncSetAttribute(tgemm3_kernel, cudaFuncAttributeMaxDynamicSharedMemorySize, TG3_SMEM);
    cudaFuncSetAttribute(tgemm2_kernel, cudaFuncAttributeMaxDynamicSharedMemorySize, TG2_SMEM);

    // #0: weight splits   #1: embed
    split_all_kernel<<<(SPLIT_TOT + 255) / 256, 256>>>(Wq, Wk, Wv, Wo);
    embed_kernel<<<BT, 256>>>(tokens, tok_table, pos_emb);

    // #2-#4: QKV projections (fp16 3-term, fp16 output)
    const int gq = (BT / 128) * (Edim / 128);
    tgemm3_kernel<<<gq, 256, TG3_SMEM>>>(pxh, pxl, pwqh, pwql, bq, pqh, BT, Edim, Edim, 8);
    tgemm3_kernel<<<gq, 256, TG3_SMEM>>>(pxh, pxl, pwkh, pwkl, bk, pkh, BT, Edim, Edim, 8);
    tgemm3_kernel<<<gq, 256, TG3_SMEM>>>(pxh, pxl, pwvh, pwvl, bv, pvh, BT, Edim, Edim, 8);

    // #5: HMMA flash attention (writes oh/ol fp16 hi/lo)
    attn_h_kernel<<<dim3(Tdim / 64, Bdim * Hdim), 128>>>(pqh, pkh, pvh);

    // #6: logits (fp16 2-term)
    const int gl = (BT / 128) * (Vdim / 128);
    tgemm2_kernel<<<gl, 256, TG2_SMEM>>>(poh, pol, pwoh, bo, out, BT, Vdim, Edim, 8);

    if ((long long)out_size > (long long)BT * Vdim) {
        loss_row_kernel<<<BT, 256>>>(out, targets, prl);
        loss_reduce_kernel<<<1, 256>>>(prl, out + (size_t)BT * Vdim);
    }
}

// round 17
// speedup vs baseline: 6.4550x; 1.4479x over previous
#include <cuda_runtime.h>
#include <cuda_fp16.h>
#include <math.h>
#include <stdint.h>

#define Bdim 2
#define Tdim 2048
#define Edim 1024
#define Hdim 16
#define Ddim 64
#define Vdim 32000
#define BT   (Bdim * Tdim)   // 4096

// ---------------- scratch (static device globals; no allocation) -------------
__device__ float g_rowloss[BT];

// fp16 operands
__device__ __half g_xh[BT * Edim], g_xl[BT * Edim];
__device__ __half g_qh[BT * Edim], g_kh[BT * Edim], g_vh[BT * Edim];
__device__ __half g_oh[BT * Edim];
__device__ __half g_wqh[Edim * Edim], g_wql[Edim * Edim];
__device__ __half g_wkh[Edim * Edim], g_wkl[Edim * Edim];
__device__ __half g_wvh[Edim * Edim], g_wvl[Edim * Edim];
__device__ __half g_woh[Vdim * Edim];          // logits: single-fp16 W

// ---------------- small helpers ----------------------------------------------
__device__ __forceinline__ void split1h(float v, __half& h, __half& l) {
    h = __float2half(v);
    l = __float2half(v - __half2float(h));
}

__device__ __forceinline__ uint32_t smem_u32(const void* p) {
    uint32_t a;
    asm("{ .reg .u64 t; cvta.to.shared.u64 t, %1; cvt.u32.u64 %0, t; }" : "=r"(a) : "l"(p));
    return a;
}

__device__ __forceinline__ void ldsm4(uint32_t* r, uint32_t addr) {
    asm volatile("ldmatrix.sync.aligned.m8n8.x4.shared.b16 {%0,%1,%2,%3}, [%4];"
                 : "=r"(r[0]), "=r"(r[1]), "=r"(r[2]), "=r"(r[3]) : "r"(addr));
}

__device__ __forceinline__ void ldsm4t(uint32_t* r, uint32_t addr) {
    asm volatile("ldmatrix.sync.aligned.m8n8.x4.trans.shared.b16 {%0,%1,%2,%3}, [%4];"
                 : "=r"(r[0]), "=r"(r[1]), "=r"(r[2]), "=r"(r[3]) : "r"(addr));
}

__device__ __forceinline__ void mma16816(float* c, const uint32_t* a, const uint32_t* b) {
    asm volatile("mma.sync.aligned.m16n8k16.row.col.f32.f16.f16.f32 "
                 "{%0,%1,%2,%3}, {%4,%5,%6,%7}, {%8,%9}, {%0,%1,%2,%3};"
                 : "+f"(c[0]), "+f"(c[1]), "+f"(c[2]), "+f"(c[3])
                 : "r"(a[0]), "r"(a[1]), "r"(a[2]), "r"(a[3]), "r"(b[0]), "r"(b[1]));
}

#define CP_ASYNC16(s, g) asm volatile("cp.async.cg.shared.global [%0], [%1], 16;" :: "r"(s), "l"(g))
#define CP_COMMIT()      asm volatile("cp.async.commit_group;")
#define CP_WAIT0()       asm volatile("cp.async.wait_group 0;")

// ---------------- merged weight split: Wq/Wk/Wv -> fp16 hi+lo, Wo -> fp16 ----
#define WSPLIT_N4  (Edim * Edim / 4)
#define WO_N4      (Vdim * Edim / 4)
#define SPLIT_TOT  (3 * WSPLIT_N4 + WO_N4)
__global__ __launch_bounds__(256)
void split_all_kernel(const float* __restrict__ Wq, const float* __restrict__ Wk,
                      const float* __restrict__ Wv, const float* __restrict__ Wo) {
    int idx = blockIdx.x * 256 + threadIdx.x;
    if (idx >= SPLIT_TOT) return;
    if (idx < 3 * WSPLIT_N4) {
        int which = idx / WSPLIT_N4;
        int i = idx - which * WSPLIT_N4;
        const float* src = which == 0 ? Wq : which == 1 ? Wk : Wv;
        __half* hi = which == 0 ? g_wqh : which == 1 ? g_wkh : g_wvh;
        __half* lo = which == 0 ? g_wql : which == 1 ? g_wkl : g_wvl;
        float4 v = ((const float4*)src)[i];
        float f[4] = {v.x, v.y, v.z, v.w};
        __half h[4], l[4];
#pragma unroll
        for (int j = 0; j < 4; j++) split1h(f[j], h[j], l[j]);
        *(uint2*)(hi + (size_t)i * 4) = *(uint2*)h;
        *(uint2*)(lo + (size_t)i * 4) = *(uint2*)l;
    } else {
        int i = idx - 3 * WSPLIT_N4;
        float4 v = ((const float4*)Wo)[i];
        __half h[4] = {__float2half(v.x), __float2half(v.y),
                       __float2half(v.z), __float2half(v.w)};
        *(uint2*)(g_woh + (size_t)i * 4) = *(uint2*)h;
    }
}

// ---------------- embed: x = tok_table[tok] + pos_emb[t] -> fp16 hi/lo -------
__global__ void embed_kernel(const int* __restrict__ tokens,
                             const float* __restrict__ tok_table,
                             const float* __restrict__ pos_emb) {
    int rowi = blockIdx.x;
    int t = rowi & (Tdim - 1);
    int tok = tokens[rowi];
    const float4* tt = (const float4*)(tok_table + (size_t)tok * Edim);
    const float4* pp = (const float4*)(pos_emb + (size_t)t * Edim);
    int i = threadIdx.x;
    float4 a = tt[i], b = pp[i];
    float v[4] = {a.x + b.x, a.y + b.y, a.z + b.z, a.w + b.w};
    __half h[4], l[4];
#pragma unroll
    for (int j = 0; j < 4; j++) split1h(v[j], h[j], l[j]);
    size_t off = (size_t)rowi * Edim + i * 4;
    *(uint2*)(g_xh + off) = *(uint2*)h;
    *(uint2*)(g_xl + off) = *(uint2*)l;
}

// ---------------- shared GEMM constants --------------------------------------
#define KPB 80                      // smem bytes per row (32 fp16 + 8 pad)
#define MT_BYTES (128 * KPB)
#define TG_NSTAGE 2

// ====== fused QKV: 3-term fp16 GEMM, one launch, which = blockIdx.x/256 ======
#define TG3_STAGE (4 * MT_BYTES)
#define TG3_SMEM  (TG_NSTAGE * TG3_STAGE)   // 81920 B

__global__ __launch_bounds__(256, 2)
void qkv3_kernel(const __half* __restrict__ Ah, const __half* __restrict__ Al,
                 const __half* __restrict__ B0h, const __half* __restrict__ B0l,
                 const __half* __restrict__ B1h, const __half* __restrict__ B1l,
                 const __half* __restrict__ B2h, const __half* __restrict__ B2l,
                 const float* __restrict__ bias0, const float* __restrict__ bias1,
                 const float* __restrict__ bias2,
                 __half* __restrict__ C0, __half* __restrict__ C1, __half* __restrict__ C2,
                 int M, int N, int K, int swG) {
    extern __shared__ char smem[];
    const uint32_t sbase = smem_u32(smem);
    const int tid = threadIdx.x;
    const int lane = tid & 31, wid = tid >> 5;

    const int tilesPer = gridDim.x / 3;
    const int which = blockIdx.x / tilesPer;
    const int bidx = blockIdx.x - which * tilesPer;
    const __half* Bh = which == 0 ? B0h : which == 1 ? B1h : B2h;
    const __half* Bl = which == 0 ? B0l : which == 1 ? B1l : B2l;
    const float* bias = which == 0 ? bias0 : which == 1 ? bias1 : bias2;
    __half* C = which == 0 ? C0 : which == 1 ? C1 : C2;

    const int nt_n = N >> 7;
    const int per = swG * nt_n;
    const int grp = bidx / per, rem = bidx % per;
    const int bm = (grp * swG + rem % swG) << 7;
    const int bn = (rem / swG) << 7;

    const int r0c = tid >> 2, q0 = tid & 3;
    const int r1c = (tid + 256) >> 2, q1 = tid & 3;
    const uint32_t so00 = r0c * KPB + q0 * 16;
    const uint32_t so01 = r1c * KPB + q1 * 16;
    const char* gAh = (const char*)Ah;  const char* gAl = (const char*)Al;
    const char* gBh = (const char*)Bh;  const char* gBl = (const char*)Bl;
    const size_t ga0 = ((size_t)(bm + r0c) * K + q0 * 8) * 2;
    const size_t ga1 = ((size_t)(bm + r1c) * K + q1 * 8) * 2;
    const size_t gb0 = ((size_t)(bn + r0c) * K + q0 * 8) * 2;
    const size_t gb1 = ((size_t)(bn + r1c) * K + q1 * 8) * 2;

    const int NK = K >> 5;

#define LOAD_STAGE3(buf, kc)                                                     \
    do {                                                                         \
        const uint32_t b_ = sbase + (buf) * TG3_STAGE;                           \
        const size_t kb_ = (size_t)(kc) * 64;                                    \
        CP_ASYNC16(b_ + 0 * MT_BYTES + so00, gAh + ga0 + kb_);                   \
        CP_ASYNC16(b_ + 0 * MT_BYTES + so01, gAh + ga1 + kb_);                   \
        CP_ASYNC16(b_ + 1 * MT_BYTES + so00, gAl + ga0 + kb_);                   \
        CP_ASYNC16(b_ + 1 * MT_BYTES + so01, gAl + ga1 + kb_);                   \
        CP_ASYNC16(b_ + 2 * MT_BYTES + so00, gBh + gb0 + kb_);                   \
        CP_ASYNC16(b_ + 2 * MT_BYTES + so01, gBh + gb1 + kb_);                   \
        CP_ASYNC16(b_ + 3 * MT_BYTES + so00, gBl + gb0 + kb_);                   \
        CP_ASYNC16(b_ + 3 * MT_BYTES + so01, gBl + gb1 + kb_);                   \
    } while (0)

    const int wm = (wid >> 2) * 64;
    const int wn = (wid & 3) * 32;
    const uint32_t arow = (lane & 7) | (((lane >> 3) & 1) << 3);
    const uint32_t akoff = (lane >> 4) * 16;
    const uint32_t brow = (lane & 7) + ((lane >> 4) << 3);
    const uint32_t bkoff = ((lane >> 3) & 1) * 16;

    float acc[4][4][4];
#pragma unroll
    for (int i = 0; i < 4; i++)
#pragma unroll
        for (int j = 0; j < 4; j++)
#pragma unroll
            for (int r = 0; r < 4; r++) acc[i][j][r] = 0.f;

    LOAD_STAGE3(0, 0);
    CP_COMMIT();

    int cur = 0;
    for (int kc = 0; kc < NK; kc++) {
        CP_WAIT0();
        __syncthreads();
        const int nxt = cur ^ 1;
        if (kc + 1 < NK) {
            LOAD_STAGE3(nxt, kc + 1);
            CP_COMMIT();
        }

        const uint32_t bufA = sbase + cur * TG3_STAGE;
        const uint32_t bufB = bufA + 2 * MT_BYTES;
#pragma unroll
        for (int ks = 0; ks < 2; ks++) {
            const uint32_t koff = ks * 32;
            uint32_t af[4][4];
            uint32_t bf[4][2], bf2[4][2];
#pragma unroll
            for (int i = 0; i < 4; i++)
                ldsm4(af[i], bufA + (wm + i * 16 + arow) * KPB + koff + akoff);
#pragma unroll
            for (int jj = 0; jj < 2; jj++) {
                uint32_t bd = bufB + (wn + jj * 16 + brow) * KPB + koff + bkoff;
                uint32_t t[4];
                ldsm4(t, bd);
                bf[2 * jj][0] = t[0]; bf[2 * jj][1] = t[1];
                bf[2 * jj + 1][0] = t[2]; bf[2 * jj + 1][1] = t[3];
                ldsm4(t, bd + MT_BYTES);
                bf2[2 * jj][0] = t[0]; bf2[2 * jj][1] = t[1];
                bf2[2 * jj + 1][0] = t[2]; bf2[2 * jj + 1][1] = t[3];
            }
#pragma unroll
            for (int i = 0; i < 4; i++)
#pragma unroll
                for (int j = 0; j < 4; j++) mma16816(acc[i][j], af[i], bf[j]);
#pragma unroll
            for (int i = 0; i < 4; i++)
#pragma unroll
                for (int j = 0; j < 4; j++) mma16816(acc[i][j], af[i], bf2[j]);
#pragma unroll
            for (int i = 0; i < 4; i++)
                ldsm4(af[i], bufA + MT_BYTES + (wm + i * 16 + arow) * KPB + koff + akoff);
#pragma unroll
            for (int i = 0; i < 4; i++)
#pragma unroll
                for (int j = 0; j < 4; j++) mma16816(acc[i][j], af[i], bf[j]);
        }
        cur = nxt;
    }

    const int er = bm + wm + (lane >> 2);
    const int ec = bn + wn + 2 * (lane & 3);
#pragma unroll
    for (int i = 0; i < 4; i++) {
#pragma unroll
        for (int j = 0; j < 4; j++) {
            const int row = er + i * 16, col = ec + j * 8;
            const float b0 = bias[col], b1 = bias[col + 1];
            __half2 h0 = __floats2half2_rn(acc[i][j][0] + b0, acc[i][j][1] + b1);
            __half2 h1 = __floats2half2_rn(acc[i][j][2] + b0, acc[i][j][3] + b1);
            *(__half2*)(C + (size_t)row * N + col) = h0;
            *(__half2*)(C + (size_t)(row + 8) * N + col) = h1;
        }
    }
#undef LOAD_STAGE3
}

// ====== 1-term fp16 GEMM (logits): C = Ah*Bh^T + bias =======================
#define TG1_STAGE (2 * MT_BYTES)
#define TG1_SMEM  (TG_NSTAGE * TG1_STAGE)   // 40960 B

__global__ __launch_bounds__(256, 2)
void tgemm1_kernel(const __half* __restrict__ Ah, const __half* __restrict__ Bh,
                   const float* __restrict__ bias, float* __restrict__ C,
                   int M, int N, int K, int swG) {
    extern __shared__ char smem[];
    const uint32_t sbase = smem_u32(smem);
    const int tid = threadIdx.x;
    const int lane = tid & 31, wid = tid >> 5;

    const int nt_n = N >> 7;
    const int per = swG * nt_n;
    const int grp = blockIdx.x / per, rem = blockIdx.x % per;
    const int bm = (grp * swG + rem % swG) << 7;
    const int bn = (rem / swG) << 7;

    const int r0c = tid >> 2, q0 = tid & 3;
    const int r1c = (tid + 256) >> 2, q1 = tid & 3;
    const uint32_t so00 = r0c * KPB + q0 * 16;
    const uint32_t so01 = r1c * KPB + q1 * 16;
    const char* gAh = (const char*)Ah;
    const char* gBh = (const char*)Bh;
    const size_t ga0 = ((size_t)(bm + r0c) * K + q0 * 8) * 2;
    const size_t ga1 = ((size_t)(bm + r1c) * K + q1 * 8) * 2;
    const size_t gb0 = ((size_t)(bn + r0c) * K + q0 * 8) * 2;
    const size_t gb1 = ((size_t)(bn + r1c) * K + q1 * 8) * 2;

    const int NK = K >> 5;

#define LOAD_STAGE1(buf, kc)                                                     \
    do {                                                                         \
        const uint32_t b_ = sbase + (buf) * TG1_STAGE;                           \
        const size_t kb_ = (size_t)(kc) * 64;                                    \
        CP_ASYNC16(b_ + 0 * MT_BYTES + so00, gAh + ga0 + kb_);                   \
        CP_ASYNC16(b_ + 0 * MT_BYTES + so01, gAh + ga1 + kb_);                   \
        CP_ASYNC16(b_ + 1 * MT_BYTES + so00, gBh + gb0 + kb_);                   \
        CP_ASYNC16(b_ + 1 * MT_BYTES + so01, gBh + gb1 + kb_);                   \
    } while (0)

    const int wm = (wid >> 2) * 64;
    const int wn = (wid & 3) * 32;
    const uint32_t arow = (lane & 7) | (((lane >> 3) & 1) << 3);
    const uint32_t akoff = (lane >> 4) * 16;
    const uint32_t brow = (lane & 7) + ((lane >> 4) << 3);
    const uint32_t bkoff = ((lane >> 3) & 1) * 16;

    float acc[4][4][4];
#pragma unroll
    for (int i = 0; i < 4; i++)
#pragma unroll
        for (int j = 0; j < 4; j++)
#pragma unroll
            for (int r = 0; r < 4; r++) acc[i][j][r] = 0.f;

    LOAD_STAGE1(0, 0);
    CP_COMMIT();

    int cur = 0;
    for (int kc = 0; kc < NK; kc++) {
        CP_WAIT0();
        __syncthreads();
        const int nxt = cur ^ 1;
        if (kc + 1 < NK) {
            LOAD_STAGE1(nxt, kc + 1);
            CP_COMMIT();
        }

        const uint32_t bufA = sbase + cur * TG1_STAGE;
        const uint32_t bufB = bufA + MT_BYTES;
#pragma unroll
        for (int ks = 0; ks < 2; ks++) {
            const uint32_t koff = ks * 32;
            uint32_t af[4][4], bf[4][2];
#pragma unroll
            for (int i = 0; i < 4; i++)
                ldsm4(af[i], bufA + (wm + i * 16 + arow) * KPB + koff + akoff);
#pragma unroll
            for (int jj = 0; jj < 2; jj++) {
                uint32_t bd = bufB + (wn + jj * 16 + brow) * KPB + koff + bkoff;
                uint32_t t[4];
                ldsm4(t, bd);
                bf[2 * jj][0] = t[0]; bf[2 * jj][1] = t[1];
                bf[2 * jj + 1][0] = t[2]; bf[2 * jj + 1][1] = t[3];
            }
#pragma unroll
            for (int i = 0; i < 4; i++)
#pragma unroll
                for (int j = 0; j < 4; j++) mma16816(acc[i][j], af[i], bf[j]);
        }
        cur = nxt;
    }

    const int er = bm + wm + (lane >> 2);
    const int ec = bn + wn + 2 * (lane & 3);
#pragma unroll
    for (int i = 0; i < 4; i++) {
#pragma unroll
        for (int j = 0; j < 4; j++) {
            const int row = er + i * 16, col = ec + j * 8;
            const float b0 = bias[col], b1 = bias[col + 1];
            float2 v0 = {acc[i][j][0] + b0, acc[i][j][1] + b1};
            float2 v1 = {acc[i][j][2] + b0, acc[i][j][3] + b1};
            *(float2*)(C + (size_t)row * N + col) = v0;
            *(float2*)(C + (size_t)(row + 8) * N + col) = v1;
        }
    }
#undef LOAD_STAGE1
}

// ---------------- HMMA flash attention (causal + exact reference quirks) -----
#define AKPB 144

__global__ __launch_bounds__(128)
void attn_h_kernel(const __half* __restrict__ Q, const __half* __restrict__ K,
                   const __half* __restrict__ V) {
    __shared__ __align__(16) char smemraw[3 * 64 * AKPB];
    const uint32_t sQ = smem_u32(smemraw);
    const uint32_t sK = sQ + 64 * AKPB;
    const uint32_t sV = sK + 64 * AKPB;

    const int tid = threadIdx.x, lane = tid & 31, wid = tid >> 5;
    const int bx = gridDim.x - 1 - blockIdx.x;   // long (late) t-tiles first
    const int b = blockIdx.y >> 4, h = blockIdx.y & 15;
    const int t0 = bx << 6;
    const size_t gbase = (size_t)b * Tdim * Edim + h * 64;

#pragma unroll
    for (int i = 0; i < 4; i++) {
        int idx = tid + i * 128;
        int row = idx >> 3, seg = idx & 7;
        *(uint4*)(smemraw + row * AKPB + seg * 16) =
            *(const uint4*)(Q + gbase + (size_t)(t0 + row) * Edim + seg * 8);
    }
    __syncthreads();

    const int wm = wid << 4;
    const uint32_t arow = lane & 15;
    const uint32_t acol = (lane >> 4) * 16;
    uint32_t qf[4][4];
#pragma unroll
    for (int kk = 0; kk < 4; kk++)
        ldsm4(qf[kk], sQ + (wm + arow) * AKPB + kk * 32 + acol);

    const uint32_t brow = (lane & 7) + ((lane >> 4) << 3);
    const uint32_t bcol = ((lane >> 3) & 1) * 16;

    float of[8][4];
#pragma unroll
    for (int j = 0; j < 8; j++)
#pragma unroll
        for (int r = 0; r < 4; r++) of[j][r] = 0.f;
    float m0 = -INFINITY, m1 = -INFINITY, l0 = 0.f, l1 = 0.f;
    const int r0 = t0 + wm + (lane >> 2);

    for (int tile = 0; tile <= bx; tile++) {
        const int s0 = tile << 6;
        __syncthreads();
#pragma unroll
        for (int i = 0; i < 4; i++) {
            int idx = tid + i * 128;
            int row = idx >> 3, seg = idx & 7;
            size_t g = gbase + (size_t)(s0 + row) * Edim + seg * 8;
            *(uint4*)(smemraw + 64 * AKPB + row * AKPB + seg * 16) = *(const uint4*)(K + g);
            *(uint4*)(smemraw + 128 * AKPB + row * AKPB + seg * 16) = *(const uint4*)(V + g);
        }
        __syncthreads();

        float sf[8][4];
#pragma unroll
        for (int j = 0; j < 8; j++)
#pragma unroll
            for (int r = 0; r < 4; r++) sf[j][r] = 0.f;
#pragma unroll
        for (int kk = 0; kk < 4; kk++) {
#pragma unroll
            for (int j = 0; j < 4; j++) {
                uint32_t t[4];
                ldsm4(t, sK + (j * 16 + brow) * AKPB + kk * 32 + bcol);
                uint32_t b0[2] = {t[0], t[1]};
                uint32_t b1[2] = {t[2], t[3]};
                mma16816(sf[2 * j], qf[kk], b0);
                mma16816(sf[2 * j + 1], qf[kk], b1);
            }
        }

#pragma unroll
        for (int j = 0; j < 8; j++) {
            const int c = s0 + j * 8 + 2 * (lane & 3);
            sf[j][0] = (c     <= r0     && sf[j][0] != 0.f) ? sf[j][0] : -INFINITY;
            sf[j][1] = (c + 1 <= r0     && sf[j][1] != 0.f) ? sf[j][1] : -INFINITY;
            sf[j][2] = (c     <= r0 + 8 && sf[j][2] != 0.f) ? sf[j][2] : -INFINITY;
            sf[j][3] = (c + 1 <= r0 + 8 && sf[j][3] != 0.f) ? sf[j][3] : -INFINITY;
        }

        float mx0 = sf[0][0], mx1 = sf[0][2];
#pragma unroll
        for (int j = 0; j < 8; j++) {
            mx0 = fmaxf(mx0, fmaxf(sf[j][0], sf[j][1]));
            mx1 = fmaxf(mx1, fmaxf(sf[j][2], sf[j][3]));
        }
        mx0 = fmaxf(mx0, __shfl_xor_sync(0xffffffffu, mx0, 1));
        mx0 = fmaxf(mx0, __shfl_xor_sync(0xffffffffu, mx0, 2));
        mx1 = fmaxf(mx1, __shfl_xor_sync(0xffffffffu, mx1, 1));
        mx1 = fmaxf(mx1, __shfl_xor_sync(0xffffffffu, mx1, 2));
        const float mn0 = fmaxf(m0, mx0), mn1 = fmaxf(m1, mx1);
        const float c0 = __expf(m0 - mn0), c1 = __expf(m1 - mn1);
        m0 = mn0; m1 = mn1;

        uint32_t pa[4][4];
        float ps0 = 0.f, ps1 = 0.f;
#pragma unroll
        for (int j = 0; j < 8; j++) {
            float p0 = __expf(sf[j][0] - mn0);
            float p1 = __expf(sf[j][1] - mn0);
            float p2 = __expf(sf[j][2] - mn1);
            float p3 = __expf(sf[j][3] - mn1);
            ps0 += p0 + p1; ps1 += p2 + p3;
            __half2 h01 = __floats2half2_rn(p0, p1);
            __half2 h23 = __floats2half2_rn(p2, p3);
            pa[j >> 1][(j & 1) * 2 + 0] = *(uint32_t*)&h01;
            pa[j >> 1][(j & 1) * 2 + 1] = *(uint32_t*)&h23;
        }
        ps0 += __shfl_xor_sync(0xffffffffu, ps0, 1);
        ps0 += __shfl_xor_sync(0xffffffffu, ps0, 2);
        ps1 += __shfl_xor_sync(0xffffffffu, ps1, 1);
        ps1 += __shfl_xor_sync(0xffffffffu, ps1, 2);
        l0 = l0 * c0 + ps0;
        l1 = l1 * c1 + ps1;
#pragma unroll
        for (int j = 0; j < 8; j++) {
            of[j][0] *= c0; of[j][1] *= c0; of[j][2] *= c1; of[j][3] *= c1;
        }

#pragma unroll
        for (int ks = 0; ks < 4; ks++) {
#pragma unroll
            for (int dj = 0; dj < 4; dj++) {
                uint32_t t[4];
                ldsm4t(t, sV + (ks * 16 + brow) * AKPB + dj * 32 + bcol);
                uint32_t b0[2] = {t[0], t[2]};
                uint32_t b1[2] = {t[1], t[3]};
                mma16816(of[2 * dj], pa[ks], b0);
                mma16816(of[2 * dj + 1], pa[ks], b1);
            }
        }
    }

    // epilogue: normalize, /sqrt(D), write fp16 o (single term for logits GEMM)
    const float inv0 = 1.f / (l0 * 8.f), inv1 = 1.f / (l1 * 8.f);
    const size_t rb0 = gbase + (size_t)r0 * Edim;
    const size_t rb1 = rb0 + 8 * Edim;
#pragma unroll
    for (int j = 0; j < 8; j++) {
        const int d = j * 8 + 2 * (lane & 3);
        *(__half2*)(g_oh + rb0 + d) = __floats2half2_rn(of[j][0] * inv0, of[j][1] * inv0);
        *(__half2*)(g_oh + rb1 + d) = __floats2half2_rn(of[j][2] * inv1, of[j][3] * inv1);
    }
}

// ---------------- per-row NLL: ONE pass (online softmax) ---------------------
__global__ __launch_bounds__(256)
void loss_row_kernel(const float* __restrict__ logits,
                     const int* __restrict__ targets,
                     float* __restrict__ rowloss) {
    __shared__ float redm[256];
    __shared__ float reds[256];
    const int row = blockIdx.x, tid = threadIdx.x;
    const float* lr = logits + (size_t)row * Vdim;
    const float4* lr4 = (const float4*)lr;

    float m = -INFINITY, s = 0.f;
    for (int i = tid; i < Vdim / 4; i += 256) {
        float4 v = lr4[i];
        float m4 = fmaxf(fmaxf(v.x, v.y), fmaxf(v.z, v.w));
        float mn = fmaxf(m, m4);
        s = s * __expf(m - mn)
          + __expf(v.x - mn) + __expf(v.y - mn) + __expf(v.z - mn) + __expf(v.w - mn);
        m = mn;
    }
    redm[tid] = m; reds[tid] = s; __syncthreads();
    for (int k = 128; k > 0; k >>= 1) {
        if (tid < k) {
            float m1 = redm[tid], m2 = redm[tid + k];
            float mn = fmaxf(m1, m2);
            reds[tid] = reds[tid] * __expf(m1 - mn) + reds[tid + k] * __expf(m2 - mn);
            redm[tid] = mn;
        }
        __syncthreads();
    }
    if (tid == 0)
        rowloss[row] = (redm[0] + __logf(reds[0])) - lr[targets[row]];
}

__global__ __launch_bounds__(256)
void loss_reduce_kernel(const float* __restrict__ rowloss, float* __restrict__ out) {
    __shared__ float red[256];
    const int tid = threadIdx.x;
    float s = 0.f;
    for (int i = tid; i < BT; i += 256) s += rowloss[i];
    red[tid] = s; __syncthreads();
    for (int k = 128; k > 0; k >>= 1) {
        if (tid < k) red[tid] += red[tid + k];
        __syncthreads();
    }
    if (tid == 0) *out = red[0] / (float)BT;
}

// ---------------- launch ------------------------------------------------------
extern "C" void kernel_launch(void* const* d_in, const int* in_sizes, int n_in,
                              void* d_out, int out_size) {
    const int*   tokens    = (const int*)d_in[0];
    const int*   targets   = (const int*)d_in[1];
    const float* tok_table = (const float*)d_in[2];
    const float* pos_emb   = (const float*)d_in[3];
    const float* Wq        = (const float*)d_in[4];
    const float* bq        = (const float*)d_in[5];
    const float* Wk        = (const float*)d_in[6];
    const float* bk        = (const float*)d_in[7];
    const float* Wv        = (const float*)d_in[8];
    const float* bv        = (const float*)d_in[9];
    const float* Wo        = (const float*)d_in[10];
    const float* bo        = (const float*)d_in[11];
    float* out = (float*)d_out;

    float* prl;
    cudaGetSymbolAddress((void**)&prl, g_rowloss);

    __half *pxh, *pxl, *poh, *pqh, *pkh, *pvh;
    __half *pwqh, *pwql, *pwkh, *pwkl, *pwvh, *pwvl, *pwoh;
    cudaGetSymbolAddress((void**)&pxh, g_xh);  cudaGetSymbolAddress((void**)&pxl, g_xl);
    cudaGetSymbolAddress((void**)&poh, g_oh);
    cudaGetSymbolAddress((void**)&pqh, g_qh);
    cudaGetSymbolAddress((void**)&pkh, g_kh);
    cudaGetSymbolAddress((void**)&pvh, g_vh);
    cudaGetSymbolAddress((void**)&pwqh, g_wqh); cudaGetSymbolAddress((void**)&pwql, g_wql);
    cudaGetSymbolAddress((void**)&pwkh, g_wkh); cudaGetSymbolAddress((void**)&pwkl, g_wkl);
    cudaGetSymbolAddress((void**)&pwvh, g_wvh); cudaGetSymbolAddress((void**)&pwvl, g_wvl);
    cudaGetSymbolAddress((void**)&pwoh, g_woh);

    cudaFuncSetAttribute(qkv3_kernel, cudaFuncAttributeMaxDynamicSharedMemorySize, TG3_SMEM);
    cudaFuncSetAttribute(tgemm1_kernel, cudaFuncAttributeMaxDynamicSharedMemorySize, TG1_SMEM);

    // #0: weight splits   #1: embed
    split_all_kernel<<<(SPLIT_TOT + 255) / 256, 256>>>(Wq, Wk, Wv, Wo);
    embed_kernel<<<BT, 256>>>(tokens, tok_table, pos_emb);

    // #2: fused QKV projections (fp16 3-term, one launch, grid 768)
    const int gq = (BT / 128) * (Edim / 128);          // 256 tiles per GEMM
    qkv3_kernel<<<3 * gq, 256, TG3_SMEM>>>(pxh, pxl,
                                           pwqh, pwql, pwkh, pwkl, pwvh, pwvl,
                                           bq, bk, bv, pqh, pkh, pvh,
                                           BT, Edim, Edim, 8);

    // #3: HMMA flash attention (writes oh fp16)
    attn_h_kernel<<<dim3(Tdim / 64, Bdim * Hdim), 128>>>(pqh, pkh, pvh);

    // #4: logits (fp16 single-term)
    const int gl = (BT / 128) * (Vdim / 128);
    tgemm1_kernel<<<gl, 256, TG1_SMEM>>>(poh, pwoh, bo, out, BT, Vdim, Edim, 8);

    if ((long long)out_size > (long long)BT * Vdim) {
        loss_row_kernel<<<BT, 256>>>(out, targets, prl);
        loss_reduce_kernel<<<1, 256>>>(prl, out + (size_t)BT * Vdim);
    }
}